// round 13
// baseline (speedup 1.0000x reference)
#include <cuda_runtime.h>
#include <cuda_fp16.h>
#include <math.h>
#include <stdint.h>

#define BB 4
#define SEQ 4096
#define DIM 256
#define CHK 128
#define NCH (SEQ/CHK)      // 32
#define GAMMA 0.9865f
#define INV16 0.0625f
#define ROWS_TOT (BB*SEQ)  // 16384
#define PAD 40

// ---------------- scratch ----------------
__device__ float g_ic[SEQ];
__device__ float g_sloc[BB*NCH*DIM];
__device__ float g_sbd [BB*NCH*DIM];
__device__ float g_dinv[BB*SEQ];
__device__ float g_T[(size_t)BB*NCH*DIM*DIM];
__device__ __half g_Th[(size_t)BB*NCH*DIM*DIM];

__device__ __half g_Qh[BB*SEQ*DIM];
__device__ __half g_Ql[BB*SEQ*DIM];
__device__ __half g_Kh[BB*SEQ*DIM];
__device__ __half g_Kl[BB*SEQ*DIM];
__device__ __half g_Vh[BB*SEQ*DIM];

__device__ __half g_Wth[3*DIM*DIM];             // W^T [n][k]
__device__ __half g_Wtl[3*DIM*DIM];

// ======================= helpers =========================================
__device__ __forceinline__ uint32_t smem_u32(const void* p) {
    uint32_t a;
    asm("{ .reg .u64 t; cvta.to.shared.u64 t, %1; cvt.u32.u64 %0, t; }" : "=r"(a) : "l"(p));
    return a;
}
__device__ __forceinline__ void cpa(uint32_t d, const void* s) {
    asm volatile("cp.async.cg.shared.global [%0], [%1], 16;" :: "r"(d), "l"(s));
}
#define CPA_COMMIT asm volatile("cp.async.commit_group;" ::: "memory")
#define CPA_WAIT(n) asm volatile("cp.async.wait_group %0;" :: "n"(n) : "memory")

__device__ __forceinline__ void mma16816(float* c, const uint32_t* a, const uint32_t* b) {
    asm volatile(
        "mma.sync.aligned.m16n8k16.row.col.f32.f16.f16.f32 "
        "{%0,%1,%2,%3}, {%4,%5,%6,%7}, {%8,%9}, {%0,%1,%2,%3};"
        : "+f"(c[0]), "+f"(c[1]), "+f"(c[2]), "+f"(c[3])
        : "r"(a[0]), "r"(a[1]), "r"(a[2]), "r"(a[3]), "r"(b[0]), "r"(b[1]));
}
__device__ __forceinline__ void ldsm4(uint32_t* r, uint32_t a) {
    asm volatile("ldmatrix.sync.aligned.m8n8.x4.shared.b16 {%0,%1,%2,%3}, [%4];"
        : "=r"(r[0]), "=r"(r[1]), "=r"(r[2]), "=r"(r[3]) : "r"(a));
}
__device__ __forceinline__ void ldsm4t(uint32_t* r, uint32_t a) {
    asm volatile("ldmatrix.sync.aligned.m8n8.x4.trans.shared.b16 {%0,%1,%2,%3}, [%4];"
        : "=r"(r[0]), "=r"(r[1]), "=r"(r[2]), "=r"(r[3]) : "r"(a));
}
__device__ __forceinline__ uint32_t addr_am(uint32_t base, int lane, int m0, int k0, int L) {
    int row = m0 + (lane & 7) + ((lane >> 3) & 1)*8;
    int col = k0 + ((lane >> 4) & 1)*8;
    return base + (uint32_t)(row*L + col)*2;
}
__device__ __forceinline__ uint32_t addr_bn(uint32_t base, int lane, int n0, int k0, int L) {
    int row = n0 + (lane & 7) + ((lane >> 4) & 1)*8;
    int col = k0 + ((lane >> 3) & 1)*8;
    return base + (uint32_t)(row*L + col)*2;
}
__device__ __forceinline__ uint32_t baddr(uint32_t base, int lane, int k0, int n0, int L) {
    int row = k0 + (lane & 7) + ((lane >> 3) & 1)*8;
    int col = n0 + ((lane >> 4) & 1)*8;
    return base + (uint32_t)(row*L + col)*2;
}
__device__ __forceinline__ uint32_t aaddr_t(uint32_t base, int lane, int m0, int k0, int L) {
    int row = k0 + (lane & 7) + ((lane >> 4) & 1)*8;
    int col = m0 + ((lane >> 3) & 1)*8;
    return base + (uint32_t)(row*L + col)*2;
}
__device__ __forceinline__ uint32_t pack2(float a, float b, uint32_t& lo) {
    __half2 hh = __floats2half2_rn(a, b);
    float2 bk = __half22float2(hh);
    __half2 ll = __floats2half2_rn(a - bk.x, b - bk.y);
    lo = *(uint32_t*)&ll;
    return *(uint32_t*)&hh;
}
__device__ __forceinline__ void load8(float* f, const __half* h, const __half* l) {
    uint4 hv = *(const uint4*)h, lv = *(const uint4*)l;
    const __half2* hp = (const __half2*)&hv;
    const __half2* lp = (const __half2*)&lv;
    #pragma unroll
    for (int i = 0; i < 4; i++) {
        float2 a = __half22float2(hp[i]), bq = __half22float2(lp[i]);
        f[2*i] = a.x + bq.x; f[2*i+1] = a.y + bq.y;
    }
}
__device__ __forceinline__ void load8r(float* f, uint4 hv, uint4 lv) {
    const __half2* hp = (const __half2*)&hv;
    const __half2* lp = (const __half2*)&lv;
    #pragma unroll
    for (int i = 0; i < 4; i++) {
        float2 a = __half22float2(hp[i]), bq = __half22float2(lp[i]);
        f[2*i] = a.x + bq.x; f[2*i+1] = a.y + bq.y;
    }
}

// ---------------- K0: W split + ic ---------------------------------------
__global__ void k_prep(const float* __restrict__ Wq, const float* __restrict__ Wk,
                       const float* __restrict__ Wv) {
    int mat = blockIdx.y;
    const float* W = (mat==0) ? Wq : (mat==1 ? Wk : Wv);
    int k = blockIdx.x, n = threadIdx.x;
    float w = W[k*DIM + n];
    __half h = __float2half_rn(w);
    g_Wth[mat*DIM*DIM + n*DIM + k] = h;
    g_Wtl[mat*DIM*DIM + n*DIM + k] = __float2half_rn(w - __half2float(h));
    if (mat == 0 && k < 16) {
        int j = k*256 + n;
        float lg = logf(GAMMA);
        float gp = expf((float)(j+1)*lg);
        g_ic[j] = rsqrtf((1.0f - gp)/(1.0f - GAMMA));
    }
}

// ---------------- K1: projection — 3-pass fp16, 3-stage W ring ------------
#define P_X(p) ((p)*20480)              // XH +0, XL +10240
#define P_W(s) (40960 + (s)*20480)      // WH +0, WL +10240
#define SM_PROJ 102400
__global__ void __launch_bounds__(256,2) k_proj_mma(
    const float* __restrict__ xq, const float* __restrict__ xk, const float* __restrict__ xv,
    const float* __restrict__ bq, const float* __restrict__ bk, const float* __restrict__ bv)
{
    extern __shared__ char sm[];
    __shared__ float sl[128];
    __shared__ float wdec[128];

    int tid = threadIdx.x;
    int warp = tid >> 5, lane = tid & 31;
    int wm = warp & 1, wn = warp >> 1;
    int gr = lane >> 2, tg = lane & 3;

    int mat = blockIdx.z;
    int m0 = blockIdx.x * 128;
    int n0 = blockIdx.y * 128;

    if (tid < 128) {
        sl[tid] = 0.f;
        wdec[tid] = __expf((float)(127-tid)*logf(GAMMA)) * g_ic[(m0+tid) & (SEQ-1)];
    }

    const float* X = (mat==0) ? xq : (mat==1 ? xk : xv);
    X += (size_t)m0*DIM;
    const __half* Wh = g_Wth + mat*DIM*DIM + (size_t)n0*DIM;
    const __half* Wl = g_Wtl + mat*DIM*DIM + (size_t)n0*DIM;
    const float* bias = (mat==0) ? bq : (mat==1 ? bk : bv);
    __half* OH = ((mat==0) ? g_Qh : (mat==1 ? g_Kh : g_Vh)) + (size_t)m0*DIM;
    __half* OL = ((mat==0) ? g_Ql : g_Kl) + (size_t)m0*DIM;

    uint32_t smb = smem_u32(sm);
    float acc[4][4][4] = {};
    float4 xr[4];

    #pragma unroll
    for (int l = 0; l < 4; l++) {
        int i = tid + l*256;
        int row = i >> 3, c4 = (i & 7)*4;
        xr[l] = *(const float4*)&X[(size_t)row*DIM + c4];
    }
    #pragma unroll
    for (int s = 0; s < 2; s++) {
        #pragma unroll
        for (int l = 0; l < 2; l++) {
            int i = tid + l*256;
            int row = i >> 2, c8 = (i & 3)*8;
            cpa(smb + P_W(s) + (row*PAD + c8)*2,         &Wh[(size_t)row*DIM + s*32 + c8]);
            cpa(smb + P_W(s) + 10240 + (row*PAD + c8)*2, &Wl[(size_t)row*DIM + s*32 + c8]);
        }
        CPA_COMMIT;
    }

    for (int st = 0; st < 8; st++) {
        if (st < 7) CPA_WAIT(1); else CPA_WAIT(0);
        char* xb = sm + P_X(st & 1);
        #pragma unroll
        for (int l = 0; l < 4; l++) {
            int i = tid + l*256;
            int row = i >> 3, c4 = (i & 7)*4;
            uint32_t l01, l23;
            uint32_t h01 = pack2(xr[l].x, xr[l].y, l01);
            uint32_t h23 = pack2(xr[l].z, xr[l].w, l23);
            *(uint2*)(xb + (row*PAD + c4)*2)         = make_uint2(h01, h23);
            *(uint2*)(xb + 10240 + (row*PAD + c4)*2) = make_uint2(l01, l23);
        }
        if (st < 7) {
            int kn = (st+1)*32;
            #pragma unroll
            for (int l = 0; l < 4; l++) {
                int i = tid + l*256;
                int row = i >> 3, c4 = (i & 7)*4;
                xr[l] = *(const float4*)&X[(size_t)row*DIM + kn + c4];
            }
        }
        __syncthreads();
        if (st + 2 < 8) {
            int kn = (st+2)*32;
            uint32_t wb = smb + P_W((st+2)%3);
            #pragma unroll
            for (int l = 0; l < 2; l++) {
                int i = tid + l*256;
                int row = i >> 2, c8 = (i & 3)*8;
                cpa(wb + (row*PAD + c8)*2,         &Wh[(size_t)row*DIM + kn + c8]);
                cpa(wb + 10240 + (row*PAD + c8)*2, &Wl[(size_t)row*DIM + kn + c8]);
            }
            CPA_COMMIT;
        }
        uint32_t sXh = smb + P_X(st & 1), sXl = sXh + 10240;
        uint32_t sBh = smb + P_W(st % 3), sBl = sBh + 10240;
        #pragma unroll
        for (int ks = 0; ks < 32; ks += 16) {
            uint32_t ah[4][4], al[4][4];
            #pragma unroll
            for (int mf = 0; mf < 4; mf++) {
                ldsm4(ah[mf], addr_am(sXh, lane, wm*64 + mf*16, ks, PAD));
                ldsm4(al[mf], addr_am(sXl, lane, wm*64 + mf*16, ks, PAD));
            }
            uint32_t bh[2][4], bl[2][4];
            #pragma unroll
            for (int p = 0; p < 2; p++) {
                ldsm4(bh[p], addr_bn(sBh, lane, wn*32 + p*16, ks, PAD));
                ldsm4(bl[p], addr_bn(sBl, lane, wn*32 + p*16, ks, PAD));
            }
            #pragma unroll
            for (int nf = 0; nf < 4; nf++) {
                const uint32_t* pbh = &bh[nf>>1][(nf&1)*2];
                const uint32_t* pbl = &bl[nf>>1][(nf&1)*2];
                #pragma unroll
                for (int mf = 0; mf < 4; mf++) {
                    mma16816(acc[mf][nf], ah[mf], pbh);
                    mma16816(acc[mf][nf], ah[mf], pbl);
                    mma16816(acc[mf][nf], al[mf], pbh);
                }
            }
        }
    }

    #pragma unroll
    for (int nf = 0; nf < 4; nf++) {
        int col = n0 + wn*32 + nf*8 + tg*2;
        float b0 = bias[col], b1 = bias[col+1];
        float s0 = 0.f, s1 = 0.f;
        #pragma unroll
        for (int mf = 0; mf < 4; mf++) {
            int row = wm*64 + mf*16 + gr;
            float v00 = acc[mf][nf][0] + b0, v01 = acc[mf][nf][1] + b1;
            float v10 = acc[mf][nf][2] + b0, v11 = acc[mf][nf][3] + b1;
            uint32_t lw0, lw1;
            uint32_t hw0 = pack2(v00, v01, lw0);
            uint32_t hw1 = pack2(v10, v11, lw1);
            *(uint32_t*)&OH[(size_t)row*DIM + col]     = hw0;
            *(uint32_t*)&OH[(size_t)(row+8)*DIM + col] = hw1;
            if (mat < 2) {
                *(uint32_t*)&OL[(size_t)row*DIM + col]     = lw0;
                *(uint32_t*)&OL[(size_t)(row+8)*DIM + col] = lw1;
            }
            if (mat == 1) {
                s0 += wdec[row]*v00 + wdec[row+8]*v10;
                s1 += wdec[row]*v01 + wdec[row+8]*v11;
            }
        }
        if (mat == 1) {
            int cl = wn*32 + nf*8 + tg*2;
            atomicAdd(&sl[cl], s0);
            atomicAdd(&sl[cl+1], s1);
        }
    }
    if (mat == 1) {
        __syncthreads();
        if (tid < 128) g_sloc[blockIdx.x*DIM + n0 + tid] = sl[tid];
    }
}

// ---------------- K3: prefix combine --------------------------------------
__global__ void k_spref() {   // grid BB*8, 32 threads
    int b = blockIdx.x >> 3;
    int d = (blockIdx.x & 7)*32 + threadIdx.x;
    float v[NCH];
    #pragma unroll
    for (int c = 0; c < NCH; c++) v[c] = g_sloc[(b*NCH+c)*DIM + d];
    float gC = __expf(128.f*logf(GAMMA));
    float s = 0.f;
    #pragma unroll
    for (int c = 0; c < NCH; c++) { g_sbd[(b*NCH+c)*DIM + d] = s; s = s*gC + v[c]; }
}

// ---------------- K4: dinv via triangular MMA ------------------------------
#define D_L 0          // L tri 128x136 fp16
#define D_K 34816      // cwK 128x136 fp16
#define SM_DINV 69632
__global__ void __launch_bounds__(256,2) k_dinv() {
    extern __shared__ char sm[];
    __shared__ float rsA[CHK];
    __shared__ float rsC[CHK];
    __shared__ float cwv[CHK];
    int tid = threadIdx.x, warp = tid >> 5, lane = tid & 31;
    int gr = lane >> 2, tg = lane & 3;
    int wm = warp & 1, wn = warp >> 1;   // 2(m64) x 4(n32)
    int blk = blockIdx.x, b = blk >> 5, c = blk & 31, c0 = c*CHK;
    float lg = logf(GAMMA);
    uint32_t smb = smem_u32(sm);

    if (tid < CHK) {
        cwv[tid] = g_ic[c0 + tid]*INV16 * __expf(-(float)tid*lg);
        rsA[tid] = 0.f; rsC[tid] = 0.f;
    }
    for (int w = tid; w < 128*68; w += 256) {
        int row = w / 68, cp = (w % 68)*2;
        __half2 v = __floats2half2_rn(cp <= row ? 1.f : 0.f, cp+1 <= row ? 1.f : 0.f);
        *(uint32_t*)(sm + D_L + (row*136 + cp)*2) = *(uint32_t*)&v;
    }
    __syncthreads();

    const __half* Kh = g_Kh + (size_t)(b*SEQ + c0)*DIM;
    const __half* Kl = g_Kl + (size_t)(b*SEQ + c0)*DIM;
    const __half* Qh = g_Qh + (size_t)(b*SEQ + c0)*DIM;
    const __half* Ql = g_Ql + (size_t)(b*SEQ + c0)*DIM;

    // cross-chunk term
    {
        int row = tid >> 1, hf = tid & 1;
        int dbase = hf*128;
        size_t qp = (size_t)row*DIM + dbase;
        const float* sb = &g_sbd[blk*DIM + dbase];
        float part = 0.f;
        #pragma unroll
        for (int d = 0; d < 128; d += 8) {
            float qf[8]; load8(qf, Qh + qp + d, Ql + qp + d);
            float4 s1 = *(const float4*)&sb[d], s2 = *(const float4*)&sb[d+4];
            part += qf[0]*s1.x + qf[1]*s1.y + qf[2]*s1.z + qf[3]*s1.w
                  + qf[4]*s2.x + qf[5]*s2.y + qf[6]*s2.z + qf[7]*s2.w;
        }
        atomicAdd(&rsC[row], part * __expf((float)(row+1)*lg) * INV16);
    }

    for (int half = 0; half < 2; half++) {
        int d0 = half*128;
        if (half) __syncthreads();   // MMA reads of D_K done
        // stage cwK [j=0..127][d0..d0+127]: 2048 uint4 over 256 threads = 8 each
        #pragma unroll
        for (int l = 0; l < 8; l++) {
            int u = tid + l*256;
            int row = u >> 4, c8 = (u & 15)*8;
            size_t gp = (size_t)row*DIM + d0 + c8;
            float f[8]; load8(f, Kh + gp, Kl + gp);
            float w = cwv[row];
            __half2 h0 = __floats2half2_rn(f[0]*w, f[1]*w);
            __half2 h1 = __floats2half2_rn(f[2]*w, f[3]*w);
            __half2 h2 = __floats2half2_rn(f[4]*w, f[5]*w);
            __half2 h3 = __floats2half2_rn(f[6]*w, f[7]*w);
            uint4 pk = make_uint4(*(uint32_t*)&h0, *(uint32_t*)&h1, *(uint32_t*)&h2, *(uint32_t*)&h3);
            *(uint4*)(sm + D_K + (row*136 + c8)*2) = pk;
        }
        __syncthreads();
        // P = L @ cwK
        float acc[4][4][4] = {};
        for (int ks = 0; ks < 128; ks += 16) {
            uint32_t ah[4][4];
            #pragma unroll
            for (int mf = 0; mf < 4; mf++)
                ldsm4(ah[mf], addr_am(smb + D_L, lane, wm*64 + mf*16, ks, 136));
            uint32_t bh[2][4];
            #pragma unroll
            for (int p = 0; p < 2; p++)
                ldsm4t(bh[p], baddr(smb + D_K, lane, ks, wn*32 + p*16, 136));
            #pragma unroll
            for (int nf = 0; nf < 4; nf++) {
                const uint32_t* pb = &bh[nf>>1][(nf&1)*2];
                #pragma unroll
                for (int mf = 0; mf < 4; mf++) mma16816(acc[mf][nf], ah[mf], pb);
            }
        }
        // dot with Q rows
        #pragma unroll
        for (int mf = 0; mf < 4; mf++) {
            int i1 = wm*64 + mf*16 + gr, i2 = i1 + 8;
            float p1 = 0.f, p2 = 0.f;
            #pragma unroll
            for (int nf = 0; nf < 4; nf++) {
                int d = d0 + wn*32 + nf*8 + tg*2;
                uint32_t qh1 = *(const uint32_t*)&Qh[(size_t)i1*DIM + d];
                uint32_t ql1 = *(const uint32_t*)&Ql[(size_t)i1*DIM + d];
                uint32_t qh2 = *(const uint32_t*)&Qh[(size_t)i2*DIM + d];
                uint32_t ql2 = *(const uint32_t*)&Ql[(size_t)i2*DIM + d];
                float2 a1 = __half22float2(*(__half2*)&qh1), b1 = __half22float2(*(__half2*)&ql1);
                float2 a2 = __half22float2(*(__half2*)&qh2), b2 = __half22float2(*(__half2*)&ql2);
                p1 += acc[mf][nf][0]*(a1.x+b1.x) + acc[mf][nf][1]*(a1.y+b1.y);
                p2 += acc[mf][nf][2]*(a2.x+b2.x) + acc[mf][nf][3]*(a2.y+b2.y);
            }
            p1 += __shfl_xor_sync(0xffffffffu, p1, 1);
            p1 += __shfl_xor_sync(0xffffffffu, p1, 2);
            p2 += __shfl_xor_sync(0xffffffffu, p2, 1);
            p2 += __shfl_xor_sync(0xffffffffu, p2, 2);
            if (tg == 0) {
                atomicAdd(&rsA[i1], p1);
                atomicAdd(&rsA[i2], p2);
            }
        }
    }
    __syncthreads();
    if (tid < CHK) {
        float tot = __expf((float)tid*lg)*rsA[tid] + rsC[tid];
        g_dinv[b*SEQ + c0 + tid] = 1.0f / fmaxf(fabsf(tot), 1.0f);
    }
}

// ---------------- K5: chunk-local T — 2-pass (wK split, Vh only) ----------
#define T_K(p) ((p)*17408)
#define T_V(s) (34816 + (s)*8704)
#define SM_TLOC 60928
__global__ void __launch_bounds__(256,2) k_tloc() {
    extern __shared__ char sm[];
    __shared__ float w2[CHK];
    int tid = threadIdx.x, lane = tid & 31, warp = tid >> 5;
    int gr = lane >> 2, tg = lane & 3;
    int wm = warp >> 1, wn = warp & 1;
    int blk = blockIdx.x, b = blk >> 5, c = blk & 31, c0 = c*CHK;
    int d1t = blockIdx.y*128, d2t = blockIdx.z*128;
    uint32_t smb = smem_u32(sm);

    const __half *Kh = g_Kh + (size_t)(b*SEQ + c0)*DIM + d1t;
    const __half *Kl = g_Kl + (size_t)(b*SEQ + c0)*DIM + d1t;
    const __half *Vh = g_Vh + (size_t)(b*SEQ + c0)*DIM + d2t;

    if (tid < CHK) {
        int gj = c0 + tid;
        w2[tid] = __expf((float)(127-tid)*logf(GAMMA)) * g_ic[gj]*INV16*g_dinv[b*SEQ+gj];
    }

    uint4 khr[2], klr[2];
    #pragma unroll
    for (int l = 0; l < 2; l++) {
        int u = tid + l*256;
        int row = u >> 4, c8 = (u & 15)*8;
        khr[l] = *(const uint4*)(Kh + (size_t)row*DIM + c8);
        klr[l] = *(const uint4*)(Kl + (size_t)row*DIM + c8);
    }
    #pragma unroll
    for (int s = 0; s < 2; s++) {
        #pragma unroll
        for (int l = 0; l < 2; l++) {
            int u = tid + l*256;
            int row = u >> 4, c8 = (u & 15)*8;
            cpa(smb + T_V(s) + (uint32_t)(row*136 + c8)*2, Vh + (size_t)(s*32+row)*DIM + c8);
        }
        CPA_COMMIT;
    }
    __syncthreads();

    float acc[2][8][4] = {};

    for (int st = 0; st < 4; st++) {
        int j0 = st*32;
        if (st < 3) CPA_WAIT(1); else CPA_WAIT(0);
        char* kb = sm + T_K(st & 1);
        #pragma unroll
        for (int l = 0; l < 2; l++) {
            int u = tid + l*256;
            int row = u >> 4, c8 = (u & 15)*8;
            float f[8]; load8r(f, khr[l], klr[l]);
            float w = w2[j0 + row];
            uint32_t hw[4], lw[4];
            #pragma unroll
            for (int i2 = 0; i2 < 4; i2++) hw[i2] = pack2(f[2*i2]*w, f[2*i2+1]*w, lw[i2]);
            *(uint4*)(kb + (row*136 + c8)*2)        = *(uint4*)hw;
            *(uint4*)(kb + 8704 + (row*136 + c8)*2) = *(uint4*)lw;
        }
        if (st < 3) {
            int jn = j0 + 32;
            #pragma unroll
            for (int l = 0; l < 2; l++) {
                int u = tid + l*256;
                int row = u >> 4, c8 = (u & 15)*8;
                khr[l] = *(const uint4*)(Kh + (size_t)(jn+row)*DIM + c8);
                klr[l] = *(const uint4*)(Kl + (size_t)(jn+row)*DIM + c8);
            }
        }
        __syncthreads();
        if (st + 2 < 4) {
            int jn = (st+2)*32;
            uint32_t vb = smb + T_V((st+2)%3);
            #pragma unroll
            for (int l = 0; l < 2; l++) {
                int u = tid + l*256;
                int row = u >> 4, c8 = (u & 15)*8;
                cpa(vb + (uint32_t)(row*136 + c8)*2, Vh + (size_t)(jn+row)*DIM + c8);
            }
            CPA_COMMIT;
        }
        uint32_t kbase = smb + T_K(st & 1);
        uint32_t vb = smb + T_V(st % 3);
        #pragma unroll
        for (int ks = 0; ks < 32; ks += 16) {
            uint32_t ah[2][4], al[2][4];
            #pragma unroll
            for (int mf = 0; mf < 2; mf++) {
                ldsm4t(ah[mf], aaddr_t(kbase, lane, wm*32 + mf*16, ks, 136));
                ldsm4t(al[mf], aaddr_t(kbase + 8704, lane, wm*32 + mf*16, ks, 136));
            }
            #pragma unroll
            for (int nfp = 0; nfp < 4; nfp++) {
                uint32_t bh[4];
                ldsm4t(bh, baddr(vb, lane, ks, wn*64 + nfp*16, 136));
                #pragma unroll
                for (int mf = 0; mf < 2; mf++) {
                    mma16816(acc[mf][2*nfp],   ah[mf], bh);
                    mma16816(acc[mf][2*nfp+1], ah[mf], bh+2);
                    mma16816(acc[mf][2*nfp],   al[mf], bh);
                    mma16816(acc[mf][2*nfp+1], al[mf], bh+2);
                }
            }
        }
    }
    #pragma unroll
    for (int mf = 0; mf < 2; mf++) {
        int d1 = d1t + wm*32 + mf*16 + gr;
        #pragma unroll
        for (int nf = 0; nf < 8; nf++) {
            int d2 = d2t + wn*64 + nf*8 + tg*2;
            *(float2*)&g_T[((size_t)blk*DIM + d1)*DIM + d2]     = make_float2(acc[mf][nf][0], acc[mf][nf][1]);
            *(float2*)&g_T[((size_t)blk*DIM + d1 + 8)*DIM + d2] = make_float2(acc[mf][nf][2], acc[mf][nf][3]);
        }
    }
}

// ---------------- K6: prefix of T -> fp16 ---------------------------------
__global__ void k_tpref() {
    int idx = blockIdx.x*256 + threadIdx.x;
    int b   = idx >> 16;
    int off = idx & 65535;
    float v[NCH];
    #pragma unroll
    for (int c = 0; c < NCH; c++) v[c] = g_T[(((size_t)(b*NCH + c)) << 16) + off];
    float gC = __expf(128.f*logf(GAMMA));
    float t = 0.f;
    #pragma unroll
    for (int c = 0; c < NCH; c++) {
        size_t p = (((size_t)(b*NCH + c)) << 16) + off;
        g_Th[p] = __float2half_rn(t);
        t = t*gC + v[c];
    }
}

// ---------------- K7: fused S + B1 + B2 (S never leaves smem) -------------
#define O_ST 0                              // S tile: hi +0, lo +34816 (128x136)
#define O_RB 69632
#define OA_BUF(s) (O_RB + (s)*30720)        // QH +0, QL +10240, KH +20480
#define OB_V(s)   (O_RB + (s)*16896)        // VH 32x264
#define OB_Q(p)   (O_RB + (p)*20480)        // QH +0, QL +10240
#define OB_T(s)   (O_RB + 40960 + (s)*16896)
#define SM_KOUT 192512
__global__ void __launch_bounds__(512,1) k_out(float* __restrict__ out) {
    extern __shared__ char sm[];
    __shared__ float rowg[CHK];
    __shared__ float cw[CHK];
    __shared__ float dv[CHK];
    int tid = threadIdx.x, lane = tid & 31, warp = tid >> 5;
    int gr = lane >> 2, tg = lane & 3;
    int wm = warp & 3, wn = warp >> 2;   // 4x4 warps
    int blk = blockIdx.x, b = blk >> 5, c = blk & 31, c0 = c*CHK;
    float lg = logf(GAMMA);
    uint32_t smb = smem_u32(sm);

    const __half *Qh = g_Qh + (size_t)(b*SEQ + c0)*DIM;
    const __half *Ql = g_Ql + (size_t)(b*SEQ + c0)*DIM;
    const __half *Kh = g_Kh + (size_t)(b*SEQ + c0)*DIM;
    const __half *Vh = g_Vh + (size_t)(b*SEQ + c0)*DIM;
    const __half *Th = g_Th + (size_t)blk*65536;

    {
        int row = tid >> 2, c8 = (tid & 3)*8;
        uint32_t so = (uint32_t)(row*PAD + c8)*2;
        #pragma unroll
        for (int s = 0; s < 3; s++) {
            size_t go = (size_t)row*DIM + s*32 + c8;
            uint32_t bb = smb + OA_BUF(s);
            cpa(bb + so,         Qh + go);
            cpa(bb + 10240 + so, Ql + go);
            cpa(bb + 20480 + so, Kh + go);
            CPA_COMMIT;
        }
    }
    if (tid < CHK) {
        rowg[tid] = __expf((float)tid * lg);
        cw[tid]   = g_ic[c0 + tid]*INV16 * __expf(-(float)tid * lg);
        dv[tid]   = g_dinv[b*SEQ + c0 + tid];
    }
    __syncthreads();

    // ---- phase A: S = mask(Q K^T) -> smem tile ----
    float accA[2][4][4] = {};
    for (int st = 0; st < 8; st++) {
        if (st < 6) CPA_WAIT(2); else if (st == 6) CPA_WAIT(1); else CPA_WAIT(0);
        __syncthreads();
        if (st + 3 < 8) {
            int en = (st+3)*32;
            uint32_t bb = smb + OA_BUF((st+3)&3);
            int row = tid >> 2, c8 = (tid & 3)*8;
            uint32_t so = (uint32_t)(row*PAD + c8)*2;
            size_t go = (size_t)row*DIM + en + c8;
            cpa(bb + so,         Qh + go);
            cpa(bb + 10240 + so, Ql + go);
            cpa(bb + 20480 + so, Kh + go);
            CPA_COMMIT;
        }
        uint32_t cb = smb + OA_BUF(st & 3);
        #pragma unroll
        for (int ks = 0; ks < 32; ks += 16) {
            uint32_t ah[2][4], al[2][4];
            #pragma unroll
            for (int mf = 0; mf < 2; mf++) {
                ldsm4(ah[mf], addr_am(cb, lane, wm*32 + mf*16, ks, PAD));
                ldsm4(al[mf], addr_am(cb + 10240, lane, wm*32 + mf*16, ks, PAD));
            }
            uint32_t bh[2][4];
            #pragma unroll
            for (int p = 0; p < 2; p++)
                ldsm4(bh[p], addr_bn(cb + 20480, lane, wn*32 + p*16, ks, PAD));
            #pragma unroll
            for (int nf = 0; nf < 4; nf++) {
                const uint32_t* pbh = &bh[nf>>1][(nf&1)*2];
                #pragma unroll
                for (int mf = 0; mf < 2; mf++) {
                    mma16816(accA[mf][nf], ah[mf], pbh);
                    mma16816(accA[mf][nf], al[mf], pbh);
                }
            }
        }
    }
    #pragma unroll
    for (int mf = 0; mf < 2; mf++) {
        int i1 = wm*32 + mf*16 + gr, i2 = i1 + 8;
        float r1 = rowg[i1], r2 = rowg[i2];
        #pragma unroll
        for (int nf = 0; nf < 4; nf++) {
            int j = wn*32 + nf*8 + tg*2;
            float w0 = cw[j]*dv[j], w1 = cw[j+1]*dv[j+1];
            float v0 = (i1 >= j)   ? accA[mf][nf][0]*r1*w0 : 0.f;
            float v1 = (i1 >= j+1) ? accA[mf][nf][1]*r1*w1 : 0.f;
            float v2 = (i2 >= j)   ? accA[mf][nf][2]*r2*w0 : 0.f;
            float v3 = (i2 >= j+1) ? accA[mf][nf][3]*r2*w1 : 0.f;
            uint32_t lw;
            uint32_t hw = pack2(v0, v1, lw);
            *(uint32_t*)(sm + O_ST + (i1*136 + j)*2)         = hw;
            *(uint32_t*)(sm + O_ST + 34816 + (i1*136 + j)*2) = lw;
            hw = pack2(v2, v3, lw);
            *(uint32_t*)(sm + O_ST + (i2*136 + j)*2)         = hw;
            *(uint32_t*)(sm + O_ST + 34816 + (i2*136 + j)*2) = lw;
        }
    }
    __syncthreads();

    // ---- phase B1: out_acc = S(smem) @ V ----
    #pragma unroll
    for (int s = 0; s < 2; s++) {
        uint32_t bb = smb + OB_V(s);
        #pragma unroll
        for (int l = 0; l < 2; l++) {
            int u = tid + l*512;
            int row = u >> 5, c8 = (u & 31)*8;
            cpa(bb + (uint32_t)(row*264 + c8)*2, Vh + (size_t)(s*32+row)*DIM + c8);
        }
        CPA_COMMIT;
    }

    float acc[2][8][4] = {};
    for (int st = 0; st < 4; st++) {
        if (st < 3) CPA_WAIT(1); else CPA_WAIT(0);
        __syncthreads();
        if (st + 2 < 4) {
            int kn = (st+2)*32;
            uint32_t bb = smb + OB_V((st+2)%3);
            #pragma unroll
            for (int l = 0; l < 2; l++) {
                int u = tid + l*512;
                int row = u >> 5, c8 = (u & 31)*8;
                cpa(bb + (uint32_t)(row*264 + c8)*2, Vh + (size_t)(kn+row)*DIM + c8);
            }
            CPA_COMMIT;
        }
        int k0 = st*32;
        uint32_t vb = smb + OB_V(st % 3);
        #pragma unroll
        for (int ks = 0; ks < 32; ks += 16) {
            uint32_t ah[2][4], al[2][4];
            #pragma unroll
            for (int mf = 0; mf < 2; mf++) {
                ldsm4(ah[mf], addr_am(smb + O_ST, lane, wm*32 + mf*16, k0 + ks, 136));
                ldsm4(al[mf], addr_am(smb + O_ST + 34816, lane, wm*32 + mf*16, k0 + ks, 136));
            }
            #pragma unroll
            for (int nfp = 0; nfp < 4; nfp++) {
                uint32_t bh[4];
                ldsm4t(bh, baddr(vb, lane, ks, wn*64 + nfp*16, 264));
                #pragma unroll
                for (int mf = 0; mf < 2; mf++) {
                    mma16816(acc[mf][2*nfp],   ah[mf], bh);
                    mma16816(acc[mf][2*nfp+1], ah[mf], bh+2);
                    mma16816(acc[mf][2*nfp],   al[mf], bh);
                    mma16816(acc[mf][2*nfp+1], al[mf], bh+2);
                }
            }
        }
    }
    __syncthreads();

    // ---- phase B2: += (g^{i+1} Q) @ T_prefix ----
    uint4 qhr, qlr;
    {
        int row = tid >> 2, c8 = (tid & 3)*8;
        qhr = *(const uint4*)(Qh + (size_t)row*DIM + c8);
        qlr = *(const uint4*)(Ql + (size_t)row*DIM + c8);
    }
    #pragma unroll
    for (int s = 0; s < 2; s++) {
        uint32_t bb = smb + OB_T(s);
        #pragma unroll
        for (int l = 0; l < 2; l++) {
            int u = tid + l*512;
            int row = u >> 5, c8 = (u & 31)*8;
            cpa(bb + (uint32_t)(row*264 + c8)*2, Th + (size_t)(s*32+row)*DIM + c8);
        }
        CPA_COMMIT;
    }

    for (int st = 0; st < 8; st++) {
        if (st < 7) CPA_WAIT(1); else CPA_WAIT(0);
        char* qb = sm + OB_Q(st & 1);
        {
            int row = tid >> 2, c8 = (tid & 3)*8;
            float f[8]; load8r(f, qhr, qlr);
            float rG = rowg[row]*GAMMA;
            uint32_t hw[4], lw[4];
            #pragma unroll
            for (int i2 = 0; i2 < 4; i2++) hw[i2] = pack2(f[2*i2]*rG, f[2*i2+1]*rG, lw[i2]);
            *(uint4*)(qb + (row*PAD + c8)*2)         = *(uint4*)hw;
            *(uint4*)(qb + 10240 + (row*PAD + c8)*2) = *(uint4*)lw;
        }
        if (st < 7) {
            int en = (st+1)*32;
            int row = tid >> 2, c8 = (tid & 3)*8;
            qhr = *(const uint4*)(Qh + (size_t)row*DIM + en + c8);
            qlr = *(const uint4*)(Ql + (size_t)row*DIM + en + c8);
        }
        __syncthreads();
        if (st + 2 < 8) {
            int en = (st+2)*32;
            uint32_t bb = smb + OB_T((st+2)%3);
            #pragma unroll
            for (int l = 0; l < 2; l++) {
                int u = tid + l*512;
                int row = u >> 5, c8 = (u & 31)*8;
                cpa(bb + (uint32_t)(row*264 + c8)*2, Th + (size_t)(en+row)*DIM + c8);
            }
            CPA_COMMIT;
        }
        uint32_t ab = smb + OB_Q(st & 1);
        uint32_t bb = smb + OB_T(st % 3);
        #pragma unroll
        for (int ks = 0; ks < 32; ks += 16) {
            uint32_t ah[2][4], al[2][4];
            #pragma unroll
            for (int mf = 0; mf < 2; mf++) {
                ldsm4(ah[mf], addr_am(ab, lane, wm*32 + mf*16, ks, PAD));
                ldsm4(al[mf], addr_am(ab + 10240, lane, wm*32 + mf*16, ks, PAD));
            }
            #pragma unroll
            for (int nfp = 0; nfp < 4; nfp++) {
                uint32_t bh[4];
                ldsm4t(bh, baddr(bb, lane, ks, wn*64 + nfp*16, 264));
                #pragma unroll
                for (int mf = 0; mf < 2; mf++) {
                    mma16816(acc[mf][2*nfp],   ah[mf], bh);
                    mma16816(acc[mf][2*nfp+1], ah[mf], bh+2);
                    mma16816(acc[mf][2*nfp],   al[mf], bh);
                    mma16816(acc[mf][2*nfp+1], al[mf], bh+2);
                }
            }
        }
    }

    #pragma unroll
    for (int mf = 0; mf < 2; mf++) {
        int i1 = wm*32 + mf*16 + gr;
        #pragma unroll
        for (int nf = 0; nf < 8; nf++) {
            int n = wn*64 + nf*8 + tg*2;
            *(float2*)&out[(size_t)(b*SEQ + c0 + i1)*DIM + n]     = make_float2(acc[mf][nf][0], acc[mf][nf][1]);
            *(float2*)&out[(size_t)(b*SEQ + c0 + i1 + 8)*DIM + n] = make_float2(acc[mf][nf][2], acc[mf][nf][3]);
        }
    }
}

// -------------------------------------------------------------------------
extern "C" void kernel_launch(void* const* d_in, const int* in_sizes, int n_in,
                              void* d_out, int out_size) {
    const float* xq = (const float*)d_in[0];
    const float* xk = (const float*)d_in[1];
    const float* xv = (const float*)d_in[2];
    const float* Wq = (const float*)d_in[3];
    const float* bq = (const float*)d_in[4];
    const float* Wk = (const float*)d_in[5];
    const float* bk = (const float*)d_in[6];
    const float* Wv = (const float*)d_in[7];
    const float* bv = (const float*)d_in[8];
    float* out = (float*)d_out;

    static int once = 0;
    if (!once) {
        cudaFuncSetAttribute(k_proj_mma, cudaFuncAttributeMaxDynamicSharedMemorySize, SM_PROJ);
        cudaFuncSetAttribute(k_dinv,     cudaFuncAttributeMaxDynamicSharedMemorySize, SM_DINV);
        cudaFuncSetAttribute(k_tloc,     cudaFuncAttributeMaxDynamicSharedMemorySize, SM_TLOC);
        cudaFuncSetAttribute(k_out,      cudaFuncAttributeMaxDynamicSharedMemorySize, SM_KOUT);
        once = 1;
    }

    k_prep  <<<dim3(DIM, 3), 256>>>(Wq, Wk, Wv);
    k_proj_mma<<<dim3(ROWS_TOT/128, DIM/128, 3), 256, SM_PROJ>>>(xq, xk, xv, bq, bk, bv);
    k_spref <<<BB*8, 32>>>();
    k_dinv  <<<BB*NCH, 256, SM_DINV>>>();
    k_tloc  <<<dim3(BB*NCH, 2, 2), 256, SM_TLOC>>>();
    k_tpref <<<BB*DIM*DIM/256, 256>>>();
    k_out   <<<BB*NCH, 512, SM_KOUT>>>(out);
}

// round 14
// speedup vs baseline: 1.1929x; 1.1929x over previous
#include <cuda_runtime.h>
#include <cuda_fp16.h>
#include <math.h>
#include <stdint.h>

#define BB 4
#define SEQ 4096
#define DIM 256
#define CHK 128
#define NCH (SEQ/CHK)      // 32
#define GAMMA 0.9865f
#define INV16 0.0625f
#define ROWS_TOT (BB*SEQ)  // 16384
#define PAD 40

// ---------------- scratch ----------------
__device__ float g_ic[SEQ];
__device__ float g_sloc[BB*NCH*DIM];
__device__ float g_sbd [BB*NCH*DIM];
__device__ float g_dinv[BB*SEQ];
__device__ float g_T[(size_t)BB*NCH*DIM*DIM];
__device__ __half g_Th[(size_t)BB*NCH*DIM*DIM];

__device__ __half g_Qh[BB*SEQ*DIM];
__device__ __half g_Ql[BB*SEQ*DIM];
__device__ __half g_Kh[BB*SEQ*DIM];
__device__ __half g_Kl[BB*SEQ*DIM];
__device__ __half g_Vh[BB*SEQ*DIM];

__device__ __half g_Sh[(size_t)BB*SEQ*CHK];
__device__ __half g_Sl[(size_t)BB*SEQ*CHK];

__device__ __half g_Wth[3*DIM*DIM];             // W^T [n][k], hi only

// ======================= helpers =========================================
__device__ __forceinline__ uint32_t smem_u32(const void* p) {
    uint32_t a;
    asm("{ .reg .u64 t; cvta.to.shared.u64 t, %1; cvt.u32.u64 %0, t; }" : "=r"(a) : "l"(p));
    return a;
}
__device__ __forceinline__ void cpa(uint32_t d, const void* s) {
    asm volatile("cp.async.cg.shared.global [%0], [%1], 16;" :: "r"(d), "l"(s));
}
#define CPA_COMMIT asm volatile("cp.async.commit_group;" ::: "memory")
#define CPA_WAIT(n) asm volatile("cp.async.wait_group %0;" :: "n"(n) : "memory")

__device__ __forceinline__ void mma16816(float* c, const uint32_t* a, const uint32_t* b) {
    asm volatile(
        "mma.sync.aligned.m16n8k16.row.col.f32.f16.f16.f32 "
        "{%0,%1,%2,%3}, {%4,%5,%6,%7}, {%8,%9}, {%0,%1,%2,%3};"
        : "+f"(c[0]), "+f"(c[1]), "+f"(c[2]), "+f"(c[3])
        : "r"(a[0]), "r"(a[1]), "r"(a[2]), "r"(a[3]), "r"(b[0]), "r"(b[1]));
}
__device__ __forceinline__ void ldsm4(uint32_t* r, uint32_t a) {
    asm volatile("ldmatrix.sync.aligned.m8n8.x4.shared.b16 {%0,%1,%2,%3}, [%4];"
        : "=r"(r[0]), "=r"(r[1]), "=r"(r[2]), "=r"(r[3]) : "r"(a));
}
__device__ __forceinline__ void ldsm4t(uint32_t* r, uint32_t a) {
    asm volatile("ldmatrix.sync.aligned.m8n8.x4.trans.shared.b16 {%0,%1,%2,%3}, [%4];"
        : "=r"(r[0]), "=r"(r[1]), "=r"(r[2]), "=r"(r[3]) : "r"(a));
}
__device__ __forceinline__ uint32_t addr_am(uint32_t base, int lane, int m0, int k0, int L) {
    int row = m0 + (lane & 7) + ((lane >> 3) & 1)*8;
    int col = k0 + ((lane >> 4) & 1)*8;
    return base + (uint32_t)(row*L + col)*2;
}
__device__ __forceinline__ uint32_t addr_bn(uint32_t base, int lane, int n0, int k0, int L) {
    int row = n0 + (lane & 7) + ((lane >> 4) & 1)*8;
    int col = k0 + ((lane >> 3) & 1)*8;
    return base + (uint32_t)(row*L + col)*2;
}
__device__ __forceinline__ uint32_t baddr(uint32_t base, int lane, int k0, int n0, int L) {
    int row = k0 + (lane & 7) + ((lane >> 3) & 1)*8;
    int col = n0 + ((lane >> 4) & 1)*8;
    return base + (uint32_t)(row*L + col)*2;
}
__device__ __forceinline__ uint32_t aaddr_t(uint32_t base, int lane, int m0, int k0, int L) {
    int row = k0 + (lane & 7) + ((lane >> 4) & 1)*8;
    int col = m0 + ((lane >> 3) & 1)*8;
    return base + (uint32_t)(row*L + col)*2;
}
__device__ __forceinline__ uint32_t pack2(float a, float b, uint32_t& lo) {
    __half2 hh = __floats2half2_rn(a, b);
    float2 bk = __half22float2(hh);
    __half2 ll = __floats2half2_rn(a - bk.x, b - bk.y);
    lo = *(uint32_t*)&ll;
    return *(uint32_t*)&hh;
}
__device__ __forceinline__ void load8(float* f, const __half* h, const __half* l) {
    uint4 hv = *(const uint4*)h, lv = *(const uint4*)l;
    const __half2* hp = (const __half2*)&hv;
    const __half2* lp = (const __half2*)&lv;
    #pragma unroll
    for (int i = 0; i < 4; i++) {
        float2 a = __half22float2(hp[i]), bq = __half22float2(lp[i]);
        f[2*i] = a.x + bq.x; f[2*i+1] = a.y + bq.y;
    }
}
__device__ __forceinline__ void load8r(float* f, uint4 hv, uint4 lv) {
    const __half2* hp = (const __half2*)&hv;
    const __half2* lp = (const __half2*)&lv;
    #pragma unroll
    for (int i = 0; i < 4; i++) {
        float2 a = __half22float2(hp[i]), bq = __half22float2(lp[i]);
        f[2*i] = a.x + bq.x; f[2*i+1] = a.y + bq.y;
    }
}

// ---------------- K0: W split + ic ---------------------------------------
__global__ void k_prep(const float* __restrict__ Wq, const float* __restrict__ Wk,
                       const float* __restrict__ Wv) {
    int mat = blockIdx.y;
    const float* W = (mat==0) ? Wq : (mat==1 ? Wk : Wv);
    int k = blockIdx.x, n = threadIdx.x;
    float w = W[k*DIM + n];
    g_Wth[mat*DIM*DIM + n*DIM + k] = __float2half_rn(w);
    if (mat == 0 && k < 16) {
        int j = k*256 + n;
        float lg = logf(GAMMA);
        float gp = expf((float)(j+1)*lg);
        g_ic[j] = rsqrtf((1.0f - gp)/(1.0f - GAMMA));
    }
}

// ---------------- K1: projection — 2-pass fp16 (Wh only), 3-stage ring ----
#define P_X(p) ((p)*20480)              // XH +0, XL +10240
#define P_W(s) (40960 + (s)*10240)      // WH only
#define SM_PROJ 71680
__global__ void __launch_bounds__(256,2) k_proj_mma(
    const float* __restrict__ xq, const float* __restrict__ xk, const float* __restrict__ xv,
    const float* __restrict__ bq, const float* __restrict__ bk, const float* __restrict__ bv)
{
    extern __shared__ char sm[];
    __shared__ float sl[128];
    __shared__ float wdec[128];

    int tid = threadIdx.x;
    int warp = tid >> 5, lane = tid & 31;
    int wm = warp & 1, wn = warp >> 1;
    int gr = lane >> 2, tg = lane & 3;

    int mat = blockIdx.z;
    int m0 = blockIdx.x * 128;
    int n0 = blockIdx.y * 128;

    if (tid < 128) {
        sl[tid] = 0.f;
        wdec[tid] = __expf((float)(127-tid)*logf(GAMMA)) * g_ic[(m0+tid) & (SEQ-1)];
    }

    const float* X = (mat==0) ? xq : (mat==1 ? xk : xv);
    X += (size_t)m0*DIM;
    const __half* Wh = g_Wth + mat*DIM*DIM + (size_t)n0*DIM;
    const float* bias = (mat==0) ? bq : (mat==1 ? bk : bv);
    __half* OH = ((mat==0) ? g_Qh : (mat==1 ? g_Kh : g_Vh)) + (size_t)m0*DIM;
    __half* OL = ((mat==0) ? g_Ql : g_Kl) + (size_t)m0*DIM;

    uint32_t smb = smem_u32(sm);
    float acc[4][4][4] = {};
    float4 xr[4];

    #pragma unroll
    for (int l = 0; l < 4; l++) {
        int i = tid + l*256;
        int row = i >> 3, c4 = (i & 7)*4;
        xr[l] = *(const float4*)&X[(size_t)row*DIM + c4];
    }
    #pragma unroll
    for (int s = 0; s < 2; s++) {
        #pragma unroll
        for (int l = 0; l < 2; l++) {
            int i = tid + l*256;
            int row = i >> 2, c8 = (i & 3)*8;
            cpa(smb + P_W(s) + (row*PAD + c8)*2, &Wh[(size_t)row*DIM + s*32 + c8]);
        }
        CPA_COMMIT;
    }

    for (int st = 0; st < 8; st++) {
        if (st < 7) CPA_WAIT(1); else CPA_WAIT(0);
        char* xb = sm + P_X(st & 1);
        #pragma unroll
        for (int l = 0; l < 4; l++) {
            int i = tid + l*256;
            int row = i >> 3, c4 = (i & 7)*4;
            uint32_t l01, l23;
            uint32_t h01 = pack2(xr[l].x, xr[l].y, l01);
            uint32_t h23 = pack2(xr[l].z, xr[l].w, l23);
            *(uint2*)(xb + (row*PAD + c4)*2)         = make_uint2(h01, h23);
            *(uint2*)(xb + 10240 + (row*PAD + c4)*2) = make_uint2(l01, l23);
        }
        if (st < 7) {
            int kn = (st+1)*32;
            #pragma unroll
            for (int l = 0; l < 4; l++) {
                int i = tid + l*256;
                int row = i >> 3, c4 = (i & 7)*4;
                xr[l] = *(const float4*)&X[(size_t)row*DIM + kn + c4];
            }
        }
        __syncthreads();
        if (st + 2 < 8) {
            int kn = (st+2)*32;
            uint32_t wb = smb + P_W((st+2)%3);
            #pragma unroll
            for (int l = 0; l < 2; l++) {
                int i = tid + l*256;
                int row = i >> 2, c8 = (i & 3)*8;
                cpa(wb + (row*PAD + c8)*2, &Wh[(size_t)row*DIM + kn + c8]);
            }
            CPA_COMMIT;
        }
        uint32_t sXh = smb + P_X(st & 1), sXl = sXh + 10240;
        uint32_t sBh = smb + P_W(st % 3);
        #pragma unroll
        for (int ks = 0; ks < 32; ks += 16) {
            uint32_t ah[4][4], al[4][4];
            #pragma unroll
            for (int mf = 0; mf < 4; mf++) {
                ldsm4(ah[mf], addr_am(sXh, lane, wm*64 + mf*16, ks, PAD));
                ldsm4(al[mf], addr_am(sXl, lane, wm*64 + mf*16, ks, PAD));
            }
            uint32_t bh[2][4];
            #pragma unroll
            for (int p = 0; p < 2; p++)
                ldsm4(bh[p], addr_bn(sBh, lane, wn*32 + p*16, ks, PAD));
            #pragma unroll
            for (int nf = 0; nf < 4; nf++) {
                const uint32_t* pbh = &bh[nf>>1][(nf&1)*2];
                #pragma unroll
                for (int mf = 0; mf < 4; mf++) {
                    mma16816(acc[mf][nf], ah[mf], pbh);
                    mma16816(acc[mf][nf], al[mf], pbh);
                }
            }
        }
    }

    #pragma unroll
    for (int nf = 0; nf < 4; nf++) {
        int col = n0 + wn*32 + nf*8 + tg*2;
        float b0 = bias[col], b1 = bias[col+1];
        float s0 = 0.f, s1 = 0.f;
        #pragma unroll
        for (int mf = 0; mf < 4; mf++) {
            int row = wm*64 + mf*16 + gr;
            float v00 = acc[mf][nf][0] + b0, v01 = acc[mf][nf][1] + b1;
            float v10 = acc[mf][nf][2] + b0, v11 = acc[mf][nf][3] + b1;
            uint32_t lw0, lw1;
            uint32_t hw0 = pack2(v00, v01, lw0);
            uint32_t hw1 = pack2(v10, v11, lw1);
            *(uint32_t*)&OH[(size_t)row*DIM + col]     = hw0;
            *(uint32_t*)&OH[(size_t)(row+8)*DIM + col] = hw1;
            if (mat < 2) {
                *(uint32_t*)&OL[(size_t)row*DIM + col]     = lw0;
                *(uint32_t*)&OL[(size_t)(row+8)*DIM + col] = lw1;
            }
            if (mat == 1) {
                s0 += wdec[row]*v00 + wdec[row+8]*v10;
                s1 += wdec[row]*v01 + wdec[row+8]*v11;
            }
        }
        if (mat == 1) {
            int cl = wn*32 + nf*8 + tg*2;
            atomicAdd(&sl[cl], s0);
            atomicAdd(&sl[cl+1], s1);
        }
    }
    if (mat == 1) {
        __syncthreads();
        if (tid < 128) g_sloc[blockIdx.x*DIM + n0 + tid] = sl[tid];
    }
}

// ---------------- K3: prefix combine --------------------------------------
__global__ void k_spref() {   // grid BB*8, 32 threads
    int b = blockIdx.x >> 3;
    int d = (blockIdx.x & 7)*32 + threadIdx.x;
    float v[NCH];
    #pragma unroll
    for (int c = 0; c < NCH; c++) v[c] = g_sloc[(b*NCH+c)*DIM + d];
    float gC = __expf(128.f*logf(GAMMA));
    float s = 0.f;
    #pragma unroll
    for (int c = 0; c < NCH; c++) { g_sbd[(b*NCH+c)*DIM + d] = s; s = s*gC + v[c]; }
}

// ---------------- K7a: S = mask(Q K^T), 2-pass, fused denom ---------------
#define S_BUF(s) ((s)*30720)    // QH +0, QL +10240, KH +20480
#define SM_KS 122880
__global__ void __launch_bounds__(512,1) k_S() {
    extern __shared__ char sm[];
    __shared__ float rowg[CHK];
    __shared__ float cw[CHK];
    __shared__ float rsum[CHK];
    __shared__ float dv[CHK];
    int tid = threadIdx.x, lane = tid & 31, warp = tid >> 5;
    int gr = lane >> 2, tg = lane & 3;
    int wm = warp & 3, wn = warp >> 2;   // 4x4 warps, 32(m) x 32(n)
    int blk = blockIdx.x, b = blk >> 5, c = blk & 31, c0 = c*CHK;
    float lg = logf(GAMMA);
    uint32_t smb = smem_u32(sm);

    const __half *Qh = g_Qh + (size_t)(b*SEQ + c0)*DIM;
    const __half *Ql = g_Ql + (size_t)(b*SEQ + c0)*DIM;
    const __half *Kh = g_Kh + (size_t)(b*SEQ + c0)*DIM;

    {
        int row = tid >> 2, c8 = (tid & 3)*8;
        uint32_t so = (uint32_t)(row*PAD + c8)*2;
        #pragma unroll
        for (int s = 0; s < 3; s++) {
            size_t go = (size_t)row*DIM + s*32 + c8;
            uint32_t bb = smb + S_BUF(s);
            cpa(bb + so,         Qh + go);
            cpa(bb + 10240 + so, Ql + go);
            cpa(bb + 20480 + so, Kh + go);
            CPA_COMMIT;
        }
    }

    if (tid < CHK) {
        rowg[tid] = __expf((float)tid * lg);
        cw[tid]   = g_ic[c0 + tid]*INV16 * __expf(-(float)tid * lg);
        rsum[tid] = 0.f;
    }
    __syncthreads();

    // cross-chunk row-sum term (overlaps prologue cp.async)
    {
        int row = tid >> 2, q = tid & 3;
        int dbase = q*64;
        size_t qp = (size_t)row*DIM + dbase;
        const float* sb = &g_sbd[blk*DIM + dbase];
        float part = 0.f;
        #pragma unroll
        for (int d = 0; d < 64; d += 8) {
            float qf[8]; load8(qf, Qh + qp + d, Ql + qp + d);
            float4 s1 = *(const float4*)&sb[d], s2 = *(const float4*)&sb[d+4];
            part += qf[0]*s1.x + qf[1]*s1.y + qf[2]*s1.z + qf[3]*s1.w
                  + qf[4]*s2.x + qf[5]*s2.y + qf[6]*s2.z + qf[7]*s2.w;
        }
        atomicAdd(&rsum[row], part * __expf((float)(row+1)*lg) * INV16);
    }

    float accA[2][4][4] = {};
    for (int st = 0; st < 8; st++) {
        if (st < 6) CPA_WAIT(2); else if (st == 6) CPA_WAIT(1); else CPA_WAIT(0);
        __syncthreads();
        if (st + 3 < 8) {
            int en = (st+3)*32;
            uint32_t bb = smb + S_BUF((st+3)&3);
            int row = tid >> 2, c8 = (tid & 3)*8;
            uint32_t so = (uint32_t)(row*PAD + c8)*2;
            size_t go = (size_t)row*DIM + en + c8;
            cpa(bb + so,         Qh + go);
            cpa(bb + 10240 + so, Ql + go);
            cpa(bb + 20480 + so, Kh + go);
            CPA_COMMIT;
        }
        uint32_t cb = smb + S_BUF(st & 3);
        #pragma unroll
        for (int ks = 0; ks < 32; ks += 16) {
            uint32_t ah[2][4], al[2][4];
            #pragma unroll
            for (int mf = 0; mf < 2; mf++) {
                ldsm4(ah[mf], addr_am(cb, lane, wm*32 + mf*16, ks, PAD));
                ldsm4(al[mf], addr_am(cb + 10240, lane, wm*32 + mf*16, ks, PAD));
            }
            uint32_t bh[2][4];
            #pragma unroll
            for (int p = 0; p < 2; p++)
                ldsm4(bh[p], addr_bn(cb + 20480, lane, wn*32 + p*16, ks, PAD));
            #pragma unroll
            for (int nf = 0; nf < 4; nf++) {
                const uint32_t* pbh = &bh[nf>>1][(nf&1)*2];
                #pragma unroll
                for (int mf = 0; mf < 2; mf++) {
                    mma16816(accA[mf][nf], ah[mf], pbh);
                    mma16816(accA[mf][nf], al[mf], pbh);
                }
            }
        }
    }

    // mask + decay, accumulate row sums
    #pragma unroll
    for (int mf = 0; mf < 2; mf++) {
        int i1 = wm*32 + mf*16 + gr, i2 = i1 + 8;
        float r1 = rowg[i1], r2 = rowg[i2];
        float rs1 = 0.f, rs2 = 0.f;
        #pragma unroll
        for (int nf = 0; nf < 4; nf++) {
            int j = wn*32 + nf*8 + tg*2;
            float cj0 = cw[j], cj1 = cw[j+1];
            accA[mf][nf][0] = (i1 >= j)   ? accA[mf][nf][0]*r1*cj0 : 0.f;
            accA[mf][nf][1] = (i1 >= j+1) ? accA[mf][nf][1]*r1*cj1 : 0.f;
            accA[mf][nf][2] = (i2 >= j)   ? accA[mf][nf][2]*r2*cj0 : 0.f;
            accA[mf][nf][3] = (i2 >= j+1) ? accA[mf][nf][3]*r2*cj1 : 0.f;
            rs1 += accA[mf][nf][0] + accA[mf][nf][1];
            rs2 += accA[mf][nf][2] + accA[mf][nf][3];
        }
        atomicAdd(&rsum[i1], rs1);
        atomicAdd(&rsum[i2], rs2);
    }
    __syncthreads();
    if (tid < CHK) {
        float d = 1.0f / fmaxf(fabsf(rsum[tid]), 1.0f);
        dv[tid] = d;
        g_dinv[b*SEQ + c0 + tid] = d;
    }
    __syncthreads();

    #pragma unroll
    for (int mf = 0; mf < 2; mf++) {
        int i1 = wm*32 + mf*16 + gr, i2 = i1 + 8;
        #pragma unroll
        for (int nf = 0; nf < 4; nf++) {
            int j = wn*32 + nf*8 + tg*2;
            float dj0 = dv[j], dj1 = dv[j+1];
            uint32_t lw;
            uint32_t hw = pack2(accA[mf][nf][0]*dj0, accA[mf][nf][1]*dj1, lw);
            *(uint32_t*)&g_Sh[(size_t)(blk*CHK + i1)*CHK + j] = hw;
            *(uint32_t*)&g_Sl[(size_t)(blk*CHK + i1)*CHK + j] = lw;
            hw = pack2(accA[mf][nf][2]*dj0, accA[mf][nf][3]*dj1, lw);
            *(uint32_t*)&g_Sh[(size_t)(blk*CHK + i2)*CHK + j] = hw;
            *(uint32_t*)&g_Sl[(size_t)(blk*CHK + i2)*CHK + j] = lw;
        }
    }
}

// ---------------- K5: chunk-local T — 2-pass (wK split, Vh only) ----------
#define T_K(p) ((p)*17408)
#define T_V(s) (34816 + (s)*8704)
#define SM_TLOC 60928
__global__ void __launch_bounds__(256,2) k_tloc() {
    extern __shared__ char sm[];
    __shared__ float w2[CHK];
    int tid = threadIdx.x, lane = tid & 31, warp = tid >> 5;
    int gr = lane >> 2, tg = lane & 3;
    int wm = warp >> 1, wn = warp & 1;
    int blk = blockIdx.x, b = blk >> 5, c = blk & 31, c0 = c*CHK;
    int d1t = blockIdx.y*128, d2t = blockIdx.z*128;
    uint32_t smb = smem_u32(sm);

    const __half *Kh = g_Kh + (size_t)(b*SEQ + c0)*DIM + d1t;
    const __half *Kl = g_Kl + (size_t)(b*SEQ + c0)*DIM + d1t;
    const __half *Vh = g_Vh + (size_t)(b*SEQ + c0)*DIM + d2t;

    if (tid < CHK) {
        int gj = c0 + tid;
        w2[tid] = __expf((float)(127-tid)*logf(GAMMA)) * g_ic[gj]*INV16*g_dinv[b*SEQ+gj];
    }

    uint4 khr[2], klr[2];
    #pragma unroll
    for (int l = 0; l < 2; l++) {
        int u = tid + l*256;
        int row = u >> 4, c8 = (u & 15)*8;
        khr[l] = *(const uint4*)(Kh + (size_t)row*DIM + c8);
        klr[l] = *(const uint4*)(Kl + (size_t)row*DIM + c8);
    }
    #pragma unroll
    for (int s = 0; s < 2; s++) {
        #pragma unroll
        for (int l = 0; l < 2; l++) {
            int u = tid + l*256;
            int row = u >> 4, c8 = (u & 15)*8;
            cpa(smb + T_V(s) + (uint32_t)(row*136 + c8)*2, Vh + (size_t)(s*32+row)*DIM + c8);
        }
        CPA_COMMIT;
    }
    __syncthreads();

    float acc[2][8][4] = {};

    for (int st = 0; st < 4; st++) {
        int j0 = st*32;
        if (st < 3) CPA_WAIT(1); else CPA_WAIT(0);
        char* kb = sm + T_K(st & 1);
        #pragma unroll
        for (int l = 0; l < 2; l++) {
            int u = tid + l*256;
            int row = u >> 4, c8 = (u & 15)*8;
            float f[8]; load8r(f, khr[l], klr[l]);
            float w = w2[j0 + row];
            uint32_t hw[4], lw[4];
            #pragma unroll
            for (int i2 = 0; i2 < 4; i2++) hw[i2] = pack2(f[2*i2]*w, f[2*i2+1]*w, lw[i2]);
            *(uint4*)(kb + (row*136 + c8)*2)        = *(uint4*)hw;
            *(uint4*)(kb + 8704 + (row*136 + c8)*2) = *(uint4*)lw;
        }
        if (st < 3) {
            int jn = j0 + 32;
            #pragma unroll
            for (int l = 0; l < 2; l++) {
                int u = tid + l*256;
                int row = u >> 4, c8 = (u & 15)*8;
                khr[l] = *(const uint4*)(Kh + (size_t)(jn+row)*DIM + c8);
                klr[l] = *(const uint4*)(Kl + (size_t)(jn+row)*DIM + c8);
            }
        }
        __syncthreads();
        if (st + 2 < 4) {
            int jn = (st+2)*32;
            uint32_t vb = smb + T_V((st+2)%3);
            #pragma unroll
            for (int l = 0; l < 2; l++) {
                int u = tid + l*256;
                int row = u >> 4, c8 = (u & 15)*8;
                cpa(vb + (uint32_t)(row*136 + c8)*2, Vh + (size_t)(jn+row)*DIM + c8);
            }
            CPA_COMMIT;
        }
        uint32_t kbase = smb + T_K(st & 1);
        uint32_t vb = smb + T_V(st % 3);
        #pragma unroll
        for (int ks = 0; ks < 32; ks += 16) {
            uint32_t ah[2][4], al[2][4];
            #pragma unroll
            for (int mf = 0; mf < 2; mf++) {
                ldsm4t(ah[mf], aaddr_t(kbase, lane, wm*32 + mf*16, ks, 136));
                ldsm4t(al[mf], aaddr_t(kbase + 8704, lane, wm*32 + mf*16, ks, 136));
            }
            #pragma unroll
            for (int nfp = 0; nfp < 4; nfp++) {
                uint32_t bh[4];
                ldsm4t(bh, baddr(vb, lane, ks, wn*64 + nfp*16, 136));
                #pragma unroll
                for (int mf = 0; mf < 2; mf++) {
                    mma16816(acc[mf][2*nfp],   ah[mf], bh);
                    mma16816(acc[mf][2*nfp+1], ah[mf], bh+2);
                    mma16816(acc[mf][2*nfp],   al[mf], bh);
                    mma16816(acc[mf][2*nfp+1], al[mf], bh+2);
                }
            }
        }
    }
    #pragma unroll
    for (int mf = 0; mf < 2; mf++) {
        int d1 = d1t + wm*32 + mf*16 + gr;
        #pragma unroll
        for (int nf = 0; nf < 8; nf++) {
            int d2 = d2t + wn*64 + nf*8 + tg*2;
            *(float2*)&g_T[((size_t)blk*DIM + d1)*DIM + d2]     = make_float2(acc[mf][nf][0], acc[mf][nf][1]);
            *(float2*)&g_T[((size_t)blk*DIM + d1 + 8)*DIM + d2] = make_float2(acc[mf][nf][2], acc[mf][nf][3]);
        }
    }
}

// ---------------- K6: prefix of T -> fp16 ---------------------------------
__global__ void k_tpref() {
    int idx = blockIdx.x*256 + threadIdx.x;
    int b   = idx >> 16;
    int off = idx & 65535;
    float v[NCH];
    #pragma unroll
    for (int c = 0; c < NCH; c++) v[c] = g_T[(((size_t)(b*NCH + c)) << 16) + off];
    float gC = __expf(128.f*logf(GAMMA));
    float t = 0.f;
    #pragma unroll
    for (int c = 0; c < NCH; c++) {
        size_t p = (((size_t)(b*NCH + c)) << 16) + off;
        g_Th[p] = __float2half_rn(t);
        t = t*gC + v[c];
    }
}

// ---------------- K7b: out = S@V + (g^{i+1} Q)@T — 2-pass -----------------
#define B1_S(s) ((s)*37376)             // SH +0, SL +10240, VH +20480 (16896)
#define B2_Q(p) ((p)*20480)             // QH +0, QL +10240
#define B2_T(s) (40960 + (s)*16896)     // TH only
#define SM_KB 112128
__global__ void __launch_bounds__(512,1) k_B(float* __restrict__ out) {
    extern __shared__ char sm[];
    __shared__ float rowGn[CHK];
    int tid = threadIdx.x, lane = tid & 31, warp = tid >> 5;
    int gr = lane >> 2, tg = lane & 3;
    int wm = warp & 3, wn = warp >> 2;   // 4x4 warps, 32(m) x 64(n)
    int blk = blockIdx.x, b = blk >> 5, c = blk & 31, c0 = c*CHK;
    uint32_t smb = smem_u32(sm);

    const __half *Sh = g_Sh + (size_t)blk*CHK*CHK;
    const __half *Sl = g_Sl + (size_t)blk*CHK*CHK;
    const __half *Vh = g_Vh + (size_t)(b*SEQ + c0)*DIM;
    const __half *Qh = g_Qh + (size_t)(b*SEQ + c0)*DIM;
    const __half *Ql = g_Ql + (size_t)(b*SEQ + c0)*DIM;
    const __half *Th = g_Th + (size_t)blk*65536;

    if (tid < CHK) rowGn[tid] = __expf((float)(tid+1) * logf(GAMMA));

    #pragma unroll
    for (int s = 0; s < 2; s++) {
        uint32_t bb = smb + B1_S(s);
        {
            int row = tid >> 2, c8 = (tid & 3)*8;
            uint32_t so = (uint32_t)(row*PAD + c8)*2;
            cpa(bb + so,         Sh + (size_t)row*CHK + s*32 + c8);
            cpa(bb + 10240 + so, Sl + (size_t)row*CHK + s*32 + c8);
        }
        #pragma unroll
        for (int l = 0; l < 2; l++) {
            int u = tid + l*512;
            int row = u >> 5, c8 = (u & 31)*8;
            cpa(bb + 20480 + (uint32_t)(row*264 + c8)*2, Vh + (size_t)(s*32+row)*DIM + c8);
        }
        CPA_COMMIT;
    }
    __syncthreads();

    float acc[2][8][4] = {};

    // ---- B1: S @ V, 4 stages, 3-ring ----
    for (int st = 0; st < 4; st++) {
        if (st < 3) CPA_WAIT(1); else CPA_WAIT(0);
        __syncthreads();
        if (st + 2 < 4) {
            int kn = (st+2)*32;
            uint32_t bb = smb + B1_S((st+2)%3);
            {
                int row = tid >> 2, c8 = (tid & 3)*8;
                uint32_t so = (uint32_t)(row*PAD + c8)*2;
                cpa(bb + so,         Sh + (size_t)row*CHK + kn + c8);
                cpa(bb + 10240 + so, Sl + (size_t)row*CHK + kn + c8);
            }
            #pragma unroll
            for (int l = 0; l < 2; l++) {
                int u = tid + l*512;
                int row = u >> 5, c8 = (u & 31)*8;
                cpa(bb + 20480 + (uint32_t)(row*264 + c8)*2, Vh + (size_t)(kn+row)*DIM + c8);
            }
            CPA_COMMIT;
        }
        uint32_t cb = smb + B1_S(st % 3);
        #pragma unroll
        for (int ks = 0; ks < 32; ks += 16) {
            uint32_t ah[2][4], al[2][4];
            #pragma unroll
            for (int mf = 0; mf < 2; mf++) {
                ldsm4(ah[mf], addr_am(cb, lane, wm*32 + mf*16, ks, PAD));
                ldsm4(al[mf], addr_am(cb + 10240, lane, wm*32 + mf*16, ks, PAD));
            }
            #pragma unroll
            for (int nfp = 0; nfp < 4; nfp++) {
                uint32_t bh[4];
                ldsm4t(bh, baddr(cb + 20480, lane, ks, wn*64 + nfp*16, 264));
                #pragma unroll
                for (int mf = 0; mf < 2; mf++) {
                    mma16816(acc[mf][2*nfp],   ah[mf], bh);
                    mma16816(acc[mf][2*nfp+1], ah[mf], bh+2);
                    mma16816(acc[mf][2*nfp],   al[mf], bh);
                    mma16816(acc[mf][2*nfp+1], al[mf], bh+2);
                }
            }
        }
    }
    __syncthreads();   // B1 reads done before B2 overwrites buffers

    // ---- B2: (g^{i+1} Q) @ T_prefix, 8 stages, 3-ring T + 2-buf STS Q ----
    uint4 qhr, qlr;
    {
        int row = tid >> 2, c8 = (tid & 3)*8;
        qhr = *(const uint4*)(Qh + (size_t)row*DIM + c8);
        qlr = *(const uint4*)(Ql + (size_t)row*DIM + c8);
    }
    #pragma unroll
    for (int s = 0; s < 2; s++) {
        uint32_t bb = smb + B2_T(s);
        #pragma unroll
        for (int l = 0; l < 2; l++) {
            int u = tid + l*512;
            int row = u >> 5, c8 = (u & 31)*8;
            cpa(bb + (uint32_t)(row*264 + c8)*2, Th + (size_t)(s*32+row)*DIM + c8);
        }
        CPA_COMMIT;
    }

    for (int st = 0; st < 8; st++) {
        if (st < 7) CPA_WAIT(1); else CPA_WAIT(0);
        char* qb = sm + B2_Q(st & 1);
        {
            int row = tid >> 2, c8 = (tid & 3)*8;
            float f[8]; load8r(f, qhr, qlr);
            float rG = rowGn[row];
            uint32_t hw[4], lw[4];
            #pragma unroll
            for (int i2 = 0; i2 < 4; i2++) hw[i2] = pack2(f[2*i2]*rG, f[2*i2+1]*rG, lw[i2]);
            *(uint4*)(qb + (row*PAD + c8)*2)         = *(uint4*)hw;
            *(uint4*)(qb + 10240 + (row*PAD + c8)*2) = *(uint4*)lw;
        }
        if (st < 7) {
            int en = (st+1)*32;
            int row = tid >> 2, c8 = (tid & 3)*8;
            qhr = *(const uint4*)(Qh + (size_t)row*DIM + en + c8);
            qlr = *(const uint4*)(Ql + (size_t)row*DIM + en + c8);
        }
        __syncthreads();
        if (st + 2 < 8) {
            int en = (st+2)*32;
            uint32_t bb = smb + B2_T((st+2)%3);
            #pragma unroll
            for (int l = 0; l < 2; l++) {
                int u = tid + l*512;
                int row = u >> 5, c8 = (u & 31)*8;
                cpa(bb + (uint32_t)(row*264 + c8)*2, Th + (size_t)(en+row)*DIM + c8);
            }
            CPA_COMMIT;
        }
        uint32_t ab = smb + B2_Q(st & 1);
        uint32_t bb = smb + B2_T(st % 3);
        #pragma unroll
        for (int ks = 0; ks < 32; ks += 16) {
            uint32_t ah[2][4], al[2][4];
            #pragma unroll
            for (int mf = 0; mf < 2; mf++) {
                ldsm4(ah[mf], addr_am(ab, lane, wm*32 + mf*16, ks, PAD));
                ldsm4(al[mf], addr_am(ab + 10240, lane, wm*32 + mf*16, ks, PAD));
            }
            #pragma unroll
            for (int nfp = 0; nfp < 4; nfp++) {
                uint32_t bh[4];
                ldsm4t(bh, baddr(bb, lane, ks, wn*64 + nfp*16, 264));
                #pragma unroll
                for (int mf = 0; mf < 2; mf++) {
                    mma16816(acc[mf][2*nfp],   ah[mf], bh);
                    mma16816(acc[mf][2*nfp+1], ah[mf], bh+2);
                    mma16816(acc[mf][2*nfp],   al[mf], bh);
                    mma16816(acc[mf][2*nfp+1], al[mf], bh+2);
                }
            }
        }
    }

    #pragma unroll
    for (int mf = 0; mf < 2; mf++) {
        int i1 = wm*32 + mf*16 + gr;
        #pragma unroll
        for (int nf = 0; nf < 8; nf++) {
            int n = wn*64 + nf*8 + tg*2;
            *(float2*)&out[(size_t)(b*SEQ + c0 + i1)*DIM + n]     = make_float2(acc[mf][nf][0], acc[mf][nf][1]);
            *(float2*)&out[(size_t)(b*SEQ + c0 + i1 + 8)*DIM + n] = make_float2(acc[mf][nf][2], acc[mf][nf][3]);
        }
    }
}

// -------------------------------------------------------------------------
extern "C" void kernel_launch(void* const* d_in, const int* in_sizes, int n_in,
                              void* d_out, int out_size) {
    const float* xq = (const float*)d_in[0];
    const float* xk = (const float*)d_in[1];
    const float* xv = (const float*)d_in[2];
    const float* Wq = (const float*)d_in[3];
    const float* bq = (const float*)d_in[4];
    const float* Wk = (const float*)d_in[5];
    const float* bk = (const float*)d_in[6];
    const float* Wv = (const float*)d_in[7];
    const float* bv = (const float*)d_in[8];
    float* out = (float*)d_out;

    static int once = 0;
    if (!once) {
        cudaFuncSetAttribute(k_proj_mma, cudaFuncAttributeMaxDynamicSharedMemorySize, SM_PROJ);
        cudaFuncSetAttribute(k_S,        cudaFuncAttributeMaxDynamicSharedMemorySize, SM_KS);
        cudaFuncSetAttribute(k_tloc,     cudaFuncAttributeMaxDynamicSharedMemorySize, SM_TLOC);
        cudaFuncSetAttribute(k_B,        cudaFuncAttributeMaxDynamicSharedMemorySize, SM_KB);
        once = 1;
    }

    k_prep  <<<dim3(DIM, 3), 256>>>(Wq, Wk, Wv);
    k_proj_mma<<<dim3(ROWS_TOT/128, DIM/128, 3), 256, SM_PROJ>>>(xq, xk, xv, bq, bk, bv);
    k_spref <<<BB*8, 32>>>();
    k_S     <<<BB*NCH, 512, SM_KS>>>();
    k_tloc  <<<dim3(BB*NCH, 2, 2), 256, SM_TLOC>>>();
    k_tpref <<<BB*DIM*DIM/256, 256>>>();
    k_B     <<<BB*NCH, 512, SM_KB>>>(out);
}

// round 15
// speedup vs baseline: 1.1963x; 1.0028x over previous
#include <cuda_runtime.h>
#include <cuda_fp16.h>
#include <math.h>
#include <stdint.h>

#define BB 4
#define SEQ 4096
#define DIM 256
#define CHK 128
#define NCH (SEQ/CHK)      // 32
#define GAMMA 0.9865f
#define INV16 0.0625f
#define ROWS_TOT (BB*SEQ)  // 16384
#define PAD 40

// ---------------- scratch ----------------
__device__ float g_ic[SEQ];
__device__ float g_sloc[BB*NCH*DIM];
__device__ float g_sbd [BB*NCH*DIM];
__device__ float g_dinv[BB*SEQ];
__device__ __half g_Th[(size_t)BB*NCH*DIM*DIM];   // local T, then prefix in place

__device__ __half g_Qh[BB*SEQ*DIM];
__device__ __half g_Ql[BB*SEQ*DIM];
__device__ __half g_Kh[BB*SEQ*DIM];
__device__ __half g_Kl[BB*SEQ*DIM];
__device__ __half g_Vh[BB*SEQ*DIM];

__device__ __half g_Sh[(size_t)BB*SEQ*CHK];
__device__ __half g_Sl[(size_t)BB*SEQ*CHK];

__device__ __half g_Wth[3*DIM*DIM];             // W^T [n][k], hi only

// ======================= helpers =========================================
__device__ __forceinline__ uint32_t smem_u32(const void* p) {
    uint32_t a;
    asm("{ .reg .u64 t; cvta.to.shared.u64 t, %1; cvt.u32.u64 %0, t; }" : "=r"(a) : "l"(p));
    return a;
}
__device__ __forceinline__ void cpa(uint32_t d, const void* s) {
    asm volatile("cp.async.cg.shared.global [%0], [%1], 16;" :: "r"(d), "l"(s));
}
#define CPA_COMMIT asm volatile("cp.async.commit_group;" ::: "memory")
#define CPA_WAIT(n) asm volatile("cp.async.wait_group %0;" :: "n"(n) : "memory")

__device__ __forceinline__ void mma16816(float* c, const uint32_t* a, const uint32_t* b) {
    asm volatile(
        "mma.sync.aligned.m16n8k16.row.col.f32.f16.f16.f32 "
        "{%0,%1,%2,%3}, {%4,%5,%6,%7}, {%8,%9}, {%0,%1,%2,%3};"
        : "+f"(c[0]), "+f"(c[1]), "+f"(c[2]), "+f"(c[3])
        : "r"(a[0]), "r"(a[1]), "r"(a[2]), "r"(a[3]), "r"(b[0]), "r"(b[1]));
}
__device__ __forceinline__ void ldsm4(uint32_t* r, uint32_t a) {
    asm volatile("ldmatrix.sync.aligned.m8n8.x4.shared.b16 {%0,%1,%2,%3}, [%4];"
        : "=r"(r[0]), "=r"(r[1]), "=r"(r[2]), "=r"(r[3]) : "r"(a));
}
__device__ __forceinline__ void ldsm4t(uint32_t* r, uint32_t a) {
    asm volatile("ldmatrix.sync.aligned.m8n8.x4.trans.shared.b16 {%0,%1,%2,%3}, [%4];"
        : "=r"(r[0]), "=r"(r[1]), "=r"(r[2]), "=r"(r[3]) : "r"(a));
}
__device__ __forceinline__ uint32_t addr_am(uint32_t base, int lane, int m0, int k0, int L) {
    int row = m0 + (lane & 7) + ((lane >> 3) & 1)*8;
    int col = k0 + ((lane >> 4) & 1)*8;
    return base + (uint32_t)(row*L + col)*2;
}
__device__ __forceinline__ uint32_t addr_bn(uint32_t base, int lane, int n0, int k0, int L) {
    int row = n0 + (lane & 7) + ((lane >> 4) & 1)*8;
    int col = k0 + ((lane >> 3) & 1)*8;
    return base + (uint32_t)(row*L + col)*2;
}
__device__ __forceinline__ uint32_t baddr(uint32_t base, int lane, int k0, int n0, int L) {
    int row = k0 + (lane & 7) + ((lane >> 3) & 1)*8;
    int col = n0 + ((lane >> 4) & 1)*8;
    return base + (uint32_t)(row*L + col)*2;
}
__device__ __forceinline__ uint32_t aaddr_t(uint32_t base, int lane, int m0, int k0, int L) {
    int row = k0 + (lane & 7) + ((lane >> 4) & 1)*8;
    int col = m0 + ((lane >> 3) & 1)*8;
    return base + (uint32_t)(row*L + col)*2;
}
__device__ __forceinline__ uint32_t pack2(float a, float b, uint32_t& lo) {
    __half2 hh = __floats2half2_rn(a, b);
    float2 bk = __half22float2(hh);
    __half2 ll = __floats2half2_rn(a - bk.x, b - bk.y);
    lo = *(uint32_t*)&ll;
    return *(uint32_t*)&hh;
}
__device__ __forceinline__ void load8(float* f, const __half* h, const __half* l) {
    uint4 hv = *(const uint4*)h, lv = *(const uint4*)l;
    const __half2* hp = (const __half2*)&hv;
    const __half2* lp = (const __half2*)&lv;
    #pragma unroll
    for (int i = 0; i < 4; i++) {
        float2 a = __half22float2(hp[i]), bq = __half22float2(lp[i]);
        f[2*i] = a.x + bq.x; f[2*i+1] = a.y + bq.y;
    }
}
__device__ __forceinline__ void load8r(float* f, uint4 hv, uint4 lv) {
    const __half2* hp = (const __half2*)&hv;
    const __half2* lp = (const __half2*)&lv;
    #pragma unroll
    for (int i = 0; i < 4; i++) {
        float2 a = __half22float2(hp[i]), bq = __half22float2(lp[i]);
        f[2*i] = a.x + bq.x; f[2*i+1] = a.y + bq.y;
    }
}

// ---------------- K0: W split + ic ---------------------------------------
__global__ void k_prep(const float* __restrict__ Wq, const float* __restrict__ Wk,
                       const float* __restrict__ Wv) {
    int mat = blockIdx.y;
    const float* W = (mat==0) ? Wq : (mat==1 ? Wk : Wv);
    int k = blockIdx.x, n = threadIdx.x;
    float w = W[k*DIM + n];
    g_Wth[mat*DIM*DIM + n*DIM + k] = __float2half_rn(w);
    if (mat == 0 && k < 16) {
        int j = k*256 + n;
        float lg = logf(GAMMA);
        float gp = expf((float)(j+1)*lg);
        g_ic[j] = rsqrtf((1.0f - gp)/(1.0f - GAMMA));
    }
}

// ---------------- K1: projection — 2-pass fp16 (Wh only), 3-stage ring ----
#define P_X(p) ((p)*20480)              // XH +0, XL +10240
#define P_W(s) (40960 + (s)*10240)      // WH only
#define SM_PROJ 71680
__global__ void __launch_bounds__(256,2) k_proj_mma(
    const float* __restrict__ xq, const float* __restrict__ xk, const float* __restrict__ xv,
    const float* __restrict__ bq, const float* __restrict__ bk, const float* __restrict__ bv)
{
    extern __shared__ char sm[];
    __shared__ float sl[128];
    __shared__ float wdec[128];

    int tid = threadIdx.x;
    int warp = tid >> 5, lane = tid & 31;
    int wm = warp & 1, wn = warp >> 1;
    int gr = lane >> 2, tg = lane & 3;

    int mat = blockIdx.z;
    int m0 = blockIdx.x * 128;
    int n0 = blockIdx.y * 128;

    if (tid < 128) {
        sl[tid] = 0.f;
        wdec[tid] = __expf((float)(127-tid)*logf(GAMMA)) * g_ic[(m0+tid) & (SEQ-1)];
    }

    const float* X = (mat==0) ? xq : (mat==1 ? xk : xv);
    X += (size_t)m0*DIM;
    const __half* Wh = g_Wth + mat*DIM*DIM + (size_t)n0*DIM;
    const float* bias = (mat==0) ? bq : (mat==1 ? bk : bv);
    __half* OH = ((mat==0) ? g_Qh : (mat==1 ? g_Kh : g_Vh)) + (size_t)m0*DIM;
    __half* OL = ((mat==0) ? g_Ql : g_Kl) + (size_t)m0*DIM;

    uint32_t smb = smem_u32(sm);
    float acc[4][4][4] = {};
    float4 xr[4];

    #pragma unroll
    for (int l = 0; l < 4; l++) {
        int i = tid + l*256;
        int row = i >> 3, c4 = (i & 7)*4;
        xr[l] = *(const float4*)&X[(size_t)row*DIM + c4];
    }
    #pragma unroll
    for (int s = 0; s < 2; s++) {
        #pragma unroll
        for (int l = 0; l < 2; l++) {
            int i = tid + l*256;
            int row = i >> 2, c8 = (i & 3)*8;
            cpa(smb + P_W(s) + (row*PAD + c8)*2, &Wh[(size_t)row*DIM + s*32 + c8]);
        }
        CPA_COMMIT;
    }

    for (int st = 0; st < 8; st++) {
        if (st < 7) CPA_WAIT(1); else CPA_WAIT(0);
        char* xb = sm + P_X(st & 1);
        #pragma unroll
        for (int l = 0; l < 4; l++) {
            int i = tid + l*256;
            int row = i >> 3, c4 = (i & 7)*4;
            uint32_t l01, l23;
            uint32_t h01 = pack2(xr[l].x, xr[l].y, l01);
            uint32_t h23 = pack2(xr[l].z, xr[l].w, l23);
            *(uint2*)(xb + (row*PAD + c4)*2)         = make_uint2(h01, h23);
            *(uint2*)(xb + 10240 + (row*PAD + c4)*2) = make_uint2(l01, l23);
        }
        if (st < 7) {
            int kn = (st+1)*32;
            #pragma unroll
            for (int l = 0; l < 4; l++) {
                int i = tid + l*256;
                int row = i >> 3, c4 = (i & 7)*4;
                xr[l] = *(const float4*)&X[(size_t)row*DIM + kn + c4];
            }
        }
        __syncthreads();
        if (st + 2 < 8) {
            int kn = (st+2)*32;
            uint32_t wb = smb + P_W((st+2)%3);
            #pragma unroll
            for (int l = 0; l < 2; l++) {
                int i = tid + l*256;
                int row = i >> 2, c8 = (i & 3)*8;
                cpa(wb + (row*PAD + c8)*2, &Wh[(size_t)row*DIM + kn + c8]);
            }
            CPA_COMMIT;
        }
        uint32_t sXh = smb + P_X(st & 1), sXl = sXh + 10240;
        uint32_t sBh = smb + P_W(st % 3);
        #pragma unroll
        for (int ks = 0; ks < 32; ks += 16) {
            uint32_t ah[4][4], al[4][4];
            #pragma unroll
            for (int mf = 0; mf < 4; mf++) {
                ldsm4(ah[mf], addr_am(sXh, lane, wm*64 + mf*16, ks, PAD));
                ldsm4(al[mf], addr_am(sXl, lane, wm*64 + mf*16, ks, PAD));
            }
            uint32_t bh[2][4];
            #pragma unroll
            for (int p = 0; p < 2; p++)
                ldsm4(bh[p], addr_bn(sBh, lane, wn*32 + p*16, ks, PAD));
            #pragma unroll
            for (int nf = 0; nf < 4; nf++) {
                const uint32_t* pbh = &bh[nf>>1][(nf&1)*2];
                #pragma unroll
                for (int mf = 0; mf < 4; mf++) {
                    mma16816(acc[mf][nf], ah[mf], pbh);
                    mma16816(acc[mf][nf], al[mf], pbh);
                }
            }
        }
    }

    #pragma unroll
    for (int nf = 0; nf < 4; nf++) {
        int col = n0 + wn*32 + nf*8 + tg*2;
        float b0 = bias[col], b1 = bias[col+1];
        float s0 = 0.f, s1 = 0.f;
        #pragma unroll
        for (int mf = 0; mf < 4; mf++) {
            int row = wm*64 + mf*16 + gr;
            float v00 = acc[mf][nf][0] + b0, v01 = acc[mf][nf][1] + b1;
            float v10 = acc[mf][nf][2] + b0, v11 = acc[mf][nf][3] + b1;
            uint32_t lw0, lw1;
            uint32_t hw0 = pack2(v00, v01, lw0);
            uint32_t hw1 = pack2(v10, v11, lw1);
            *(uint32_t*)&OH[(size_t)row*DIM + col]     = hw0;
            *(uint32_t*)&OH[(size_t)(row+8)*DIM + col] = hw1;
            if (mat < 2) {
                *(uint32_t*)&OL[(size_t)row*DIM + col]     = lw0;
                *(uint32_t*)&OL[(size_t)(row+8)*DIM + col] = lw1;
            }
            if (mat == 1) {
                s0 += wdec[row]*v00 + wdec[row+8]*v10;
                s1 += wdec[row]*v01 + wdec[row+8]*v11;
            }
        }
        if (mat == 1) {
            int cl = wn*32 + nf*8 + tg*2;
            atomicAdd(&sl[cl], s0);
            atomicAdd(&sl[cl+1], s1);
        }
    }
    if (mat == 1) {
        __syncthreads();
        if (tid < 128) g_sloc[blockIdx.x*DIM + n0 + tid] = sl[tid];
    }
}

// ---------------- K3: prefix combine --------------------------------------
__global__ void k_spref() {   // grid BB*8, 32 threads
    int b = blockIdx.x >> 3;
    int d = (blockIdx.x & 7)*32 + threadIdx.x;
    float v[NCH];
    #pragma unroll
    for (int c = 0; c < NCH; c++) v[c] = g_sloc[(b*NCH+c)*DIM + d];
    float gC = __expf(128.f*logf(GAMMA));
    float s = 0.f;
    #pragma unroll
    for (int c = 0; c < NCH; c++) { g_sbd[(b*NCH+c)*DIM + d] = s; s = s*gC + v[c]; }
}

// ---------------- K7a: S = mask(Q K^T), 2-pass, fused denom ---------------
#define S_BUF(s) ((s)*30720)    // QH +0, QL +10240, KH +20480
#define SM_KS 122880
__global__ void __launch_bounds__(512,1) k_S() {
    extern __shared__ char sm[];
    __shared__ float rowg[CHK];
    __shared__ float cw[CHK];
    __shared__ float rsum[CHK];
    __shared__ float dv[CHK];
    int tid = threadIdx.x, lane = tid & 31, warp = tid >> 5;
    int gr = lane >> 2, tg = lane & 3;
    int wm = warp & 3, wn = warp >> 2;   // 4x4 warps, 32(m) x 32(n)
    int blk = blockIdx.x, b = blk >> 5, c = blk & 31, c0 = c*CHK;
    float lg = logf(GAMMA);
    uint32_t smb = smem_u32(sm);

    const __half *Qh = g_Qh + (size_t)(b*SEQ + c0)*DIM;
    const __half *Ql = g_Ql + (size_t)(b*SEQ + c0)*DIM;
    const __half *Kh = g_Kh + (size_t)(b*SEQ + c0)*DIM;

    {
        int row = tid >> 2, c8 = (tid & 3)*8;
        uint32_t so = (uint32_t)(row*PAD + c8)*2;
        #pragma unroll
        for (int s = 0; s < 3; s++) {
            size_t go = (size_t)row*DIM + s*32 + c8;
            uint32_t bb = smb + S_BUF(s);
            cpa(bb + so,         Qh + go);
            cpa(bb + 10240 + so, Ql + go);
            cpa(bb + 20480 + so, Kh + go);
            CPA_COMMIT;
        }
    }

    if (tid < CHK) {
        rowg[tid] = __expf((float)tid * lg);
        cw[tid]   = g_ic[c0 + tid]*INV16 * __expf(-(float)tid * lg);
        rsum[tid] = 0.f;
    }
    __syncthreads();

    // cross-chunk row-sum term (overlaps prologue cp.async)
    {
        int row = tid >> 2, q = tid & 3;
        int dbase = q*64;
        size_t qp = (size_t)row*DIM + dbase;
        const float* sb = &g_sbd[blk*DIM + dbase];
        float part = 0.f;
        #pragma unroll
        for (int d = 0; d < 64; d += 8) {
            float qf[8]; load8(qf, Qh + qp + d, Ql + qp + d);
            float4 s1 = *(const float4*)&sb[d], s2 = *(const float4*)&sb[d+4];
            part += qf[0]*s1.x + qf[1]*s1.y + qf[2]*s1.z + qf[3]*s1.w
                  + qf[4]*s2.x + qf[5]*s2.y + qf[6]*s2.z + qf[7]*s2.w;
        }
        atomicAdd(&rsum[row], part * __expf((float)(row+1)*lg) * INV16);
    }

    float accA[2][4][4] = {};
    for (int st = 0; st < 8; st++) {
        if (st < 6) CPA_WAIT(2); else if (st == 6) CPA_WAIT(1); else CPA_WAIT(0);
        __syncthreads();
        if (st + 3 < 8) {
            int en = (st+3)*32;
            uint32_t bb = smb + S_BUF((st+3)&3);
            int row = tid >> 2, c8 = (tid & 3)*8;
            uint32_t so = (uint32_t)(row*PAD + c8)*2;
            size_t go = (size_t)row*DIM + en + c8;
            cpa(bb + so,         Qh + go);
            cpa(bb + 10240 + so, Ql + go);
            cpa(bb + 20480 + so, Kh + go);
            CPA_COMMIT;
        }
        uint32_t cb = smb + S_BUF(st & 3);
        #pragma unroll
        for (int ks = 0; ks < 32; ks += 16) {
            uint32_t ah[2][4], al[2][4];
            #pragma unroll
            for (int mf = 0; mf < 2; mf++) {
                ldsm4(ah[mf], addr_am(cb, lane, wm*32 + mf*16, ks, PAD));
                ldsm4(al[mf], addr_am(cb + 10240, lane, wm*32 + mf*16, ks, PAD));
            }
            uint32_t bh[2][4];
            #pragma unroll
            for (int p = 0; p < 2; p++)
                ldsm4(bh[p], addr_bn(cb + 20480, lane, wn*32 + p*16, ks, PAD));
            #pragma unroll
            for (int nf = 0; nf < 4; nf++) {
                const uint32_t* pbh = &bh[nf>>1][(nf&1)*2];
                #pragma unroll
                for (int mf = 0; mf < 2; mf++) {
                    mma16816(accA[mf][nf], ah[mf], pbh);
                    mma16816(accA[mf][nf], al[mf], pbh);
                }
            }
        }
    }

    // mask + decay, accumulate row sums
    #pragma unroll
    for (int mf = 0; mf < 2; mf++) {
        int i1 = wm*32 + mf*16 + gr, i2 = i1 + 8;
        float r1 = rowg[i1], r2 = rowg[i2];
        float rs1 = 0.f, rs2 = 0.f;
        #pragma unroll
        for (int nf = 0; nf < 4; nf++) {
            int j = wn*32 + nf*8 + tg*2;
            float cj0 = cw[j], cj1 = cw[j+1];
            accA[mf][nf][0] = (i1 >= j)   ? accA[mf][nf][0]*r1*cj0 : 0.f;
            accA[mf][nf][1] = (i1 >= j+1) ? accA[mf][nf][1]*r1*cj1 : 0.f;
            accA[mf][nf][2] = (i2 >= j)   ? accA[mf][nf][2]*r2*cj0 : 0.f;
            accA[mf][nf][3] = (i2 >= j+1) ? accA[mf][nf][3]*r2*cj1 : 0.f;
            rs1 += accA[mf][nf][0] + accA[mf][nf][1];
            rs2 += accA[mf][nf][2] + accA[mf][nf][3];
        }
        atomicAdd(&rsum[i1], rs1);
        atomicAdd(&rsum[i2], rs2);
    }
    __syncthreads();
    if (tid < CHK) {
        float d = 1.0f / fmaxf(fabsf(rsum[tid]), 1.0f);
        dv[tid] = d;
        g_dinv[b*SEQ + c0 + tid] = d;
    }
    __syncthreads();

    #pragma unroll
    for (int mf = 0; mf < 2; mf++) {
        int i1 = wm*32 + mf*16 + gr, i2 = i1 + 8;
        #pragma unroll
        for (int nf = 0; nf < 4; nf++) {
            int j = wn*32 + nf*8 + tg*2;
            float dj0 = dv[j], dj1 = dv[j+1];
            uint32_t lw;
            uint32_t hw = pack2(accA[mf][nf][0]*dj0, accA[mf][nf][1]*dj1, lw);
            *(uint32_t*)&g_Sh[(size_t)(blk*CHK + i1)*CHK + j] = hw;
            *(uint32_t*)&g_Sl[(size_t)(blk*CHK + i1)*CHK + j] = lw;
            hw = pack2(accA[mf][nf][2]*dj0, accA[mf][nf][3]*dj1, lw);
            *(uint32_t*)&g_Sh[(size_t)(blk*CHK + i2)*CHK + j] = hw;
            *(uint32_t*)&g_Sl[(size_t)(blk*CHK + i2)*CHK + j] = lw;
        }
    }
}

// ---------------- K5: chunk-local T — 2-pass, fp16 output ------------------
#define T_K(p) ((p)*17408)
#define T_V(s) (34816 + (s)*8704)
#define SM_TLOC 60928
__global__ void __launch_bounds__(256,2) k_tloc() {
    extern __shared__ char sm[];
    __shared__ float w2[CHK];
    int tid = threadIdx.x, lane = tid & 31, warp = tid >> 5;
    int gr = lane >> 2, tg = lane & 3;
    int wm = warp >> 1, wn = warp & 1;
    int blk = blockIdx.x, b = blk >> 5, c = blk & 31, c0 = c*CHK;
    int d1t = blockIdx.y*128, d2t = blockIdx.z*128;
    uint32_t smb = smem_u32(sm);

    const __half *Kh = g_Kh + (size_t)(b*SEQ + c0)*DIM + d1t;
    const __half *Kl = g_Kl + (size_t)(b*SEQ + c0)*DIM + d1t;
    const __half *Vh = g_Vh + (size_t)(b*SEQ + c0)*DIM + d2t;

    if (tid < CHK) {
        int gj = c0 + tid;
        w2[tid] = __expf((float)(127-tid)*logf(GAMMA)) * g_ic[gj]*INV16*g_dinv[b*SEQ+gj];
    }

    uint4 khr[2], klr[2];
    #pragma unroll
    for (int l = 0; l < 2; l++) {
        int u = tid + l*256;
        int row = u >> 4, c8 = (u & 15)*8;
        khr[l] = *(const uint4*)(Kh + (size_t)row*DIM + c8);
        klr[l] = *(const uint4*)(Kl + (size_t)row*DIM + c8);
    }
    #pragma unroll
    for (int s = 0; s < 2; s++) {
        #pragma unroll
        for (int l = 0; l < 2; l++) {
            int u = tid + l*256;
            int row = u >> 4, c8 = (u & 15)*8;
            cpa(smb + T_V(s) + (uint32_t)(row*136 + c8)*2, Vh + (size_t)(s*32+row)*DIM + c8);
        }
        CPA_COMMIT;
    }
    __syncthreads();

    float acc[2][8][4] = {};

    for (int st = 0; st < 4; st++) {
        int j0 = st*32;
        if (st < 3) CPA_WAIT(1); else CPA_WAIT(0);
        char* kb = sm + T_K(st & 1);
        #pragma unroll
        for (int l = 0; l < 2; l++) {
            int u = tid + l*256;
            int row = u >> 4, c8 = (u & 15)*8;
            float f[8]; load8r(f, khr[l], klr[l]);
            float w = w2[j0 + row];
            uint32_t hw[4], lw[4];
            #pragma unroll
            for (int i2 = 0; i2 < 4; i2++) hw[i2] = pack2(f[2*i2]*w, f[2*i2+1]*w, lw[i2]);
            *(uint4*)(kb + (row*136 + c8)*2)        = *(uint4*)hw;
            *(uint4*)(kb + 8704 + (row*136 + c8)*2) = *(uint4*)lw;
        }
        if (st < 3) {
            int jn = j0 + 32;
            #pragma unroll
            for (int l = 0; l < 2; l++) {
                int u = tid + l*256;
                int row = u >> 4, c8 = (u & 15)*8;
                khr[l] = *(const uint4*)(Kh + (size_t)(jn+row)*DIM + c8);
                klr[l] = *(const uint4*)(Kl + (size_t)(jn+row)*DIM + c8);
            }
        }
        __syncthreads();
        if (st + 2 < 4) {
            int jn = (st+2)*32;
            uint32_t vb = smb + T_V((st+2)%3);
            #pragma unroll
            for (int l = 0; l < 2; l++) {
                int u = tid + l*256;
                int row = u >> 4, c8 = (u & 15)*8;
                cpa(vb + (uint32_t)(row*136 + c8)*2, Vh + (size_t)(jn+row)*DIM + c8);
            }
            CPA_COMMIT;
        }
        uint32_t kbase = smb + T_K(st & 1);
        uint32_t vb = smb + T_V(st % 3);
        #pragma unroll
        for (int ks = 0; ks < 32; ks += 16) {
            uint32_t ah[2][4], al[2][4];
            #pragma unroll
            for (int mf = 0; mf < 2; mf++) {
                ldsm4t(ah[mf], aaddr_t(kbase, lane, wm*32 + mf*16, ks, 136));
                ldsm4t(al[mf], aaddr_t(kbase + 8704, lane, wm*32 + mf*16, ks, 136));
            }
            #pragma unroll
            for (int nfp = 0; nfp < 4; nfp++) {
                uint32_t bh[4];
                ldsm4t(bh, baddr(vb, lane, ks, wn*64 + nfp*16, 136));
                #pragma unroll
                for (int mf = 0; mf < 2; mf++) {
                    mma16816(acc[mf][2*nfp],   ah[mf], bh);
                    mma16816(acc[mf][2*nfp+1], ah[mf], bh+2);
                    mma16816(acc[mf][2*nfp],   al[mf], bh);
                    mma16816(acc[mf][2*nfp+1], al[mf], bh+2);
                }
            }
        }
    }
    // write local T as fp16 (prefix computed in place by k_tpref)
    #pragma unroll
    for (int mf = 0; mf < 2; mf++) {
        int d1 = d1t + wm*32 + mf*16 + gr;
        #pragma unroll
        for (int nf = 0; nf < 8; nf++) {
            int d2 = d2t + wn*64 + nf*8 + tg*2;
            __half2 p0 = __floats2half2_rn(acc[mf][nf][0], acc[mf][nf][1]);
            __half2 p1 = __floats2half2_rn(acc[mf][nf][2], acc[mf][nf][3]);
            *(uint32_t*)&g_Th[((size_t)blk*DIM + d1)*DIM + d2]     = *(uint32_t*)&p0;
            *(uint32_t*)&g_Th[((size_t)blk*DIM + d1 + 8)*DIM + d2] = *(uint32_t*)&p1;
        }
    }
}

// ---------------- K6: in-place prefix of T (fp16, half2-vectorized) -------
__global__ void k_tpref() {   // grid 512, 256 threads; 2 elements per thread
    int idx = blockIdx.x*256 + threadIdx.x;   // half2 index, [0, BB*32768)
    int b   = idx >> 15;
    int off = (idx & 32767)*2;
    float2 v[NCH];
    #pragma unroll
    for (int c = 0; c < NCH; c++) {
        uint32_t w = *(const uint32_t*)&g_Th[(((size_t)(b*NCH + c)) << 16) + off];
        v[c] = __half22float2(*(__half2*)&w);
    }
    float gC = __expf(128.f*logf(GAMMA));
    float t0 = 0.f, t1 = 0.f;
    #pragma unroll
    for (int c = 0; c < NCH; c++) {
        __half2 p = __floats2half2_rn(t0, t1);
        *(uint32_t*)&g_Th[(((size_t)(b*NCH + c)) << 16) + off] = *(uint32_t*)&p;
        t0 = t0*gC + v[c].x;
        t1 = t1*gC + v[c].y;
    }
}

// ---------------- K7b: out = S@V + (g^{i+1} Q)@T — 2-pass -----------------
#define B1_S(s) ((s)*37376)             // SH +0, SL +10240, VH +20480 (16896)
#define B2_Q(p) ((p)*20480)             // QH +0, QL +10240
#define B2_T(s) (40960 + (s)*16896)     // TH only
#define SM_KB 112128
__global__ void __launch_bounds__(512,1) k_B(float* __restrict__ out) {
    extern __shared__ char sm[];
    __shared__ float rowGn[CHK];
    int tid = threadIdx.x, lane = tid & 31, warp = tid >> 5;
    int gr = lane >> 2, tg = lane & 3;
    int wm = warp & 3, wn = warp >> 2;   // 4x4 warps, 32(m) x 64(n)
    int blk = blockIdx.x, b = blk >> 5, c = blk & 31, c0 = c*CHK;
    uint32_t smb = smem_u32(sm);

    const __half *Sh = g_Sh + (size_t)blk*CHK*CHK;
    const __half *Sl = g_Sl + (size_t)blk*CHK*CHK;
    const __half *Vh = g_Vh + (size_t)(b*SEQ + c0)*DIM;
    const __half *Qh = g_Qh + (size_t)(b*SEQ + c0)*DIM;
    const __half *Ql = g_Ql + (size_t)(b*SEQ + c0)*DIM;
    const __half *Th = g_Th + (size_t)blk*65536;

    if (tid < CHK) rowGn[tid] = __expf((float)(tid+1) * logf(GAMMA));

    #pragma unroll
    for (int s = 0; s < 2; s++) {
        uint32_t bb = smb + B1_S(s);
        {
            int row = tid >> 2, c8 = (tid & 3)*8;
            uint32_t so = (uint32_t)(row*PAD + c8)*2;
            cpa(bb + so,         Sh + (size_t)row*CHK + s*32 + c8);
            cpa(bb + 10240 + so, Sl + (size_t)row*CHK + s*32 + c8);
        }
        #pragma unroll
        for (int l = 0; l < 2; l++) {
            int u = tid + l*512;
            int row = u >> 5, c8 = (u & 31)*8;
            cpa(bb + 20480 + (uint32_t)(row*264 + c8)*2, Vh + (size_t)(s*32+row)*DIM + c8);
        }
        CPA_COMMIT;
    }
    __syncthreads();

    float acc[2][8][4] = {};

    // ---- B1: S @ V, 4 stages, 3-ring ----
    for (int st = 0; st < 4; st++) {
        if (st < 3) CPA_WAIT(1); else CPA_WAIT(0);
        __syncthreads();
        if (st + 2 < 4) {
            int kn = (st+2)*32;
            uint32_t bb = smb + B1_S((st+2)%3);
            {
                int row = tid >> 2, c8 = (tid & 3)*8;
                uint32_t so = (uint32_t)(row*PAD + c8)*2;
                cpa(bb + so,         Sh + (size_t)row*CHK + kn + c8);
                cpa(bb + 10240 + so, Sl + (size_t)row*CHK + kn + c8);
            }
            #pragma unroll
            for (int l = 0; l < 2; l++) {
                int u = tid + l*512;
                int row = u >> 5, c8 = (u & 31)*8;
                cpa(bb + 20480 + (uint32_t)(row*264 + c8)*2, Vh + (size_t)(kn+row)*DIM + c8);
            }
            CPA_COMMIT;
        }
        uint32_t cb = smb + B1_S(st % 3);
        #pragma unroll
        for (int ks = 0; ks < 32; ks += 16) {
            uint32_t ah[2][4], al[2][4];
            #pragma unroll
            for (int mf = 0; mf < 2; mf++) {
                ldsm4(ah[mf], addr_am(cb, lane, wm*32 + mf*16, ks, PAD));
                ldsm4(al[mf], addr_am(cb + 10240, lane, wm*32 + mf*16, ks, PAD));
            }
            #pragma unroll
            for (int nfp = 0; nfp < 4; nfp++) {
                uint32_t bh[4];
                ldsm4t(bh, baddr(cb + 20480, lane, ks, wn*64 + nfp*16, 264));
                #pragma unroll
                for (int mf = 0; mf < 2; mf++) {
                    mma16816(acc[mf][2*nfp],   ah[mf], bh);
                    mma16816(acc[mf][2*nfp+1], ah[mf], bh+2);
                    mma16816(acc[mf][2*nfp],   al[mf], bh);
                    mma16816(acc[mf][2*nfp+1], al[mf], bh+2);
                }
            }
        }
    }
    __syncthreads();   // B1 reads done before B2 overwrites buffers

    // ---- B2: (g^{i+1} Q) @ T_prefix, 8 stages, 3-ring T + 2-buf STS Q ----
    uint4 qhr, qlr;
    {
        int row = tid >> 2, c8 = (tid & 3)*8;
        qhr = *(const uint4*)(Qh + (size_t)row*DIM + c8);
        qlr = *(const uint4*)(Ql + (size_t)row*DIM + c8);
    }
    #pragma unroll
    for (int s = 0; s < 2; s++) {
        uint32_t bb = smb + B2_T(s);
        #pragma unroll
        for (int l = 0; l < 2; l++) {
            int u = tid + l*512;
            int row = u >> 5, c8 = (u & 31)*8;
            cpa(bb + (uint32_t)(row*264 + c8)*2, Th + (size_t)(s*32+row)*DIM + c8);
        }
        CPA_COMMIT;
    }

    for (int st = 0; st < 8; st++) {
        if (st < 7) CPA_WAIT(1); else CPA_WAIT(0);
        char* qb = sm + B2_Q(st & 1);
        {
            int row = tid >> 2, c8 = (tid & 3)*8;
            float f[8]; load8r(f, qhr, qlr);
            float rG = rowGn[row];
            uint32_t hw[4], lw[4];
            #pragma unroll
            for (int i2 = 0; i2 < 4; i2++) hw[i2] = pack2(f[2*i2]*rG, f[2*i2+1]*rG, lw[i2]);
            *(uint4*)(qb + (row*PAD + c8)*2)         = *(uint4*)hw;
            *(uint4*)(qb + 10240 + (row*PAD + c8)*2) = *(uint4*)lw;
        }
        if (st < 7) {
            int en = (st+1)*32;
            int row = tid >> 2, c8 = (tid & 3)*8;
            qhr = *(const uint4*)(Qh + (size_t)row*DIM + en + c8);
            qlr = *(const uint4*)(Ql + (size_t)row*DIM + en + c8);
        }
        __syncthreads();
        if (st + 2 < 8) {
            int en = (st+2)*32;
            uint32_t bb = smb + B2_T((st+2)%3);
            #pragma unroll
            for (int l = 0; l < 2; l++) {
                int u = tid + l*512;
                int row = u >> 5, c8 = (u & 31)*8;
                cpa(bb + (uint32_t)(row*264 + c8)*2, Th + (size_t)(en+row)*DIM + c8);
            }
            CPA_COMMIT;
        }
        uint32_t ab = smb + B2_Q(st & 1);
        uint32_t bb = smb + B2_T(st % 3);
        #pragma unroll
        for (int ks = 0; ks < 32; ks += 16) {
            uint32_t ah[2][4], al[2][4];
            #pragma unroll
            for (int mf = 0; mf < 2; mf++) {
                ldsm4(ah[mf], addr_am(ab, lane, wm*32 + mf*16, ks, PAD));
                ldsm4(al[mf], addr_am(ab + 10240, lane, wm*32 + mf*16, ks, PAD));
            }
            #pragma unroll
            for (int nfp = 0; nfp < 4; nfp++) {
                uint32_t bh[4];
                ldsm4t(bh, baddr(bb, lane, ks, wn*64 + nfp*16, 264));
                #pragma unroll
                for (int mf = 0; mf < 2; mf++) {
                    mma16816(acc[mf][2*nfp],   ah[mf], bh);
                    mma16816(acc[mf][2*nfp+1], ah[mf], bh+2);
                    mma16816(acc[mf][2*nfp],   al[mf], bh);
                    mma16816(acc[mf][2*nfp+1], al[mf], bh+2);
                }
            }
        }
    }

    #pragma unroll
    for (int mf = 0; mf < 2; mf++) {
        int i1 = wm*32 + mf*16 + gr;
        #pragma unroll
        for (int nf = 0; nf < 8; nf++) {
            int n = wn*64 + nf*8 + tg*2;
            *(float2*)&out[(size_t)(b*SEQ + c0 + i1)*DIM + n]     = make_float2(acc[mf][nf][0], acc[mf][nf][1]);
            *(float2*)&out[(size_t)(b*SEQ + c0 + i1 + 8)*DIM + n] = make_float2(acc[mf][nf][2], acc[mf][nf][3]);
        }
    }
}

// -------------------------------------------------------------------------
extern "C" void kernel_launch(void* const* d_in, const int* in_sizes, int n_in,
                              void* d_out, int out_size) {
    const float* xq = (const float*)d_in[0];
    const float* xk = (const float*)d_in[1];
    const float* xv = (const float*)d_in[2];
    const float* Wq = (const float*)d_in[3];
    const float* bq = (const float*)d_in[4];
    const float* Wk = (const float*)d_in[5];
    const float* bk = (const float*)d_in[6];
    const float* Wv = (const float*)d_in[7];
    const float* bv = (const float*)d_in[8];
    float* out = (float*)d_out;

    static int once = 0;
    if (!once) {
        cudaFuncSetAttribute(k_proj_mma, cudaFuncAttributeMaxDynamicSharedMemorySize, SM_PROJ);
        cudaFuncSetAttribute(k_S,        cudaFuncAttributeMaxDynamicSharedMemorySize, SM_KS);
        cudaFuncSetAttribute(k_tloc,     cudaFuncAttributeMaxDynamicSharedMemorySize, SM_TLOC);
        cudaFuncSetAttribute(k_B,        cudaFuncAttributeMaxDynamicSharedMemorySize, SM_KB);
        once = 1;
    }

    k_prep  <<<dim3(DIM, 3), 256>>>(Wq, Wk, Wv);
    k_proj_mma<<<dim3(ROWS_TOT/128, DIM/128, 3), 256, SM_PROJ>>>(xq, xk, xv, bq, bk, bv);
    k_spref <<<BB*8, 32>>>();
    k_S     <<<BB*NCH, 512, SM_KS>>>();
    k_tloc  <<<dim3(BB*NCH, 2, 2), 256, SM_TLOC>>>();
    k_tpref <<<512, 256>>>();
    k_B     <<<BB*NCH, 512, SM_KB>>>(out);
}

// round 16
// speedup vs baseline: 1.1966x; 1.0002x over previous
#include <cuda_runtime.h>
#include <cuda_fp16.h>
#include <math.h>
#include <stdint.h>

#define BB 4
#define SEQ 4096
#define DIM 256
#define CHK 128
#define NCH (SEQ/CHK)      // 32
#define GAMMA 0.9865f
#define INV16 0.0625f
#define ROWS_TOT (BB*SEQ)  // 16384
#define PAD 40

// ---------------- scratch ----------------
__device__ float g_ic[SEQ];
__device__ float g_sloc[BB*NCH*DIM];
__device__ __half g_Th[(size_t)BB*NCH*DIM*DIM];   // local T, then prefix in place

__device__ __half g_Qh[BB*SEQ*DIM];
__device__ __half g_Ql[BB*SEQ*DIM];
__device__ __half g_Kh[BB*SEQ*DIM];
__device__ __half g_Kl[BB*SEQ*DIM];
__device__ __half g_Vh[BB*SEQ*DIM];

__device__ __half g_Sh[(size_t)BB*SEQ*CHK];
__device__ __half g_Sl[(size_t)BB*SEQ*CHK];

__device__ __half g_Wth[3*DIM*DIM];             // W^T [n][k], hi only

// ======================= helpers =========================================
__device__ __forceinline__ uint32_t smem_u32(const void* p) {
    uint32_t a;
    asm("{ .reg .u64 t; cvta.to.shared.u64 t, %1; cvt.u32.u64 %0, t; }" : "=r"(a) : "l"(p));
    return a;
}
__device__ __forceinline__ void cpa(uint32_t d, const void* s) {
    asm volatile("cp.async.cg.shared.global [%0], [%1], 16;" :: "r"(d), "l"(s));
}
#define CPA_COMMIT asm volatile("cp.async.commit_group;" ::: "memory")
#define CPA_WAIT(n) asm volatile("cp.async.wait_group %0;" :: "n"(n) : "memory")

__device__ __forceinline__ void mma16816(float* c, const uint32_t* a, const uint32_t* b) {
    asm volatile(
        "mma.sync.aligned.m16n8k16.row.col.f32.f16.f16.f32 "
        "{%0,%1,%2,%3}, {%4,%5,%6,%7}, {%8,%9}, {%0,%1,%2,%3};"
        : "+f"(c[0]), "+f"(c[1]), "+f"(c[2]), "+f"(c[3])
        : "r"(a[0]), "r"(a[1]), "r"(a[2]), "r"(a[3]), "r"(b[0]), "r"(b[1]));
}
__device__ __forceinline__ void ldsm4(uint32_t* r, uint32_t a) {
    asm volatile("ldmatrix.sync.aligned.m8n8.x4.shared.b16 {%0,%1,%2,%3}, [%4];"
        : "=r"(r[0]), "=r"(r[1]), "=r"(r[2]), "=r"(r[3]) : "r"(a));
}
__device__ __forceinline__ void ldsm4t(uint32_t* r, uint32_t a) {
    asm volatile("ldmatrix.sync.aligned.m8n8.x4.trans.shared.b16 {%0,%1,%2,%3}, [%4];"
        : "=r"(r[0]), "=r"(r[1]), "=r"(r[2]), "=r"(r[3]) : "r"(a));
}
__device__ __forceinline__ uint32_t addr_am(uint32_t base, int lane, int m0, int k0, int L) {
    int row = m0 + (lane & 7) + ((lane >> 3) & 1)*8;
    int col = k0 + ((lane >> 4) & 1)*8;
    return base + (uint32_t)(row*L + col)*2;
}
__device__ __forceinline__ uint32_t addr_bn(uint32_t base, int lane, int n0, int k0, int L) {
    int row = n0 + (lane & 7) + ((lane >> 4) & 1)*8;
    int col = k0 + ((lane >> 3) & 1)*8;
    return base + (uint32_t)(row*L + col)*2;
}
__device__ __forceinline__ uint32_t baddr(uint32_t base, int lane, int k0, int n0, int L) {
    int row = k0 + (lane & 7) + ((lane >> 3) & 1)*8;
    int col = n0 + ((lane >> 4) & 1)*8;
    return base + (uint32_t)(row*L + col)*2;
}
__device__ __forceinline__ uint32_t aaddr_t(uint32_t base, int lane, int m0, int k0, int L) {
    int row = k0 + (lane & 7) + ((lane >> 4) & 1)*8;
    int col = m0 + ((lane >> 3) & 1)*8;
    return base + (uint32_t)(row*L + col)*2;
}
__device__ __forceinline__ uint32_t pack2(float a, float b, uint32_t& lo) {
    __half2 hh = __floats2half2_rn(a, b);
    float2 bk = __half22float2(hh);
    __half2 ll = __floats2half2_rn(a - bk.x, b - bk.y);
    lo = *(uint32_t*)&ll;
    return *(uint32_t*)&hh;
}
__device__ __forceinline__ void load8(float* f, const __half* h, const __half* l) {
    uint4 hv = *(const uint4*)h, lv = *(const uint4*)l;
    const __half2* hp = (const __half2*)&hv;
    const __half2* lp = (const __half2*)&lv;
    #pragma unroll
    for (int i = 0; i < 4; i++) {
        float2 a = __half22float2(hp[i]), bq = __half22float2(lp[i]);
        f[2*i] = a.x + bq.x; f[2*i+1] = a.y + bq.y;
    }
}
__device__ __forceinline__ void load8r(float* f, uint4 hv, uint4 lv) {
    const __half2* hp = (const __half2*)&hv;
    const __half2* lp = (const __half2*)&lv;
    #pragma unroll
    for (int i = 0; i < 4; i++) {
        float2 a = __half22float2(hp[i]), bq = __half22float2(lp[i]);
        f[2*i] = a.x + bq.x; f[2*i+1] = a.y + bq.y;
    }
}

// ---------------- K0: W split + ic ---------------------------------------
__global__ void k_prep(const float* __restrict__ Wq, const float* __restrict__ Wk,
                       const float* __restrict__ Wv) {
    int mat = blockIdx.y;
    const float* W = (mat==0) ? Wq : (mat==1 ? Wk : Wv);
    int k = blockIdx.x, n = threadIdx.x;
    float w = W[k*DIM + n];
    g_Wth[mat*DIM*DIM + n*DIM + k] = __float2half_rn(w);
    if (mat == 0 && k < 16) {
        int j = k*256 + n;
        float lg = logf(GAMMA);
        float gp = expf((float)(j+1)*lg);
        g_ic[j] = rsqrtf((1.0f - gp)/(1.0f - GAMMA));
    }
}

// ---------------- K1: projection — 2-pass fp16 (Wh only), 3-stage ring ----
#define P_X(p) ((p)*20480)              // XH +0, XL +10240
#define P_W(s) (40960 + (s)*10240)      // WH only
#define SM_PROJ 71680
__global__ void __launch_bounds__(256,2) k_proj_mma(
    const float* __restrict__ xq, const float* __restrict__ xk, const float* __restrict__ xv,
    const float* __restrict__ bq, const float* __restrict__ bk, const float* __restrict__ bv)
{
    extern __shared__ char sm[];
    __shared__ float sl[128];
    __shared__ float wdec[128];

    int tid = threadIdx.x;
    int warp = tid >> 5, lane = tid & 31;
    int wm = warp & 1, wn = warp >> 1;
    int gr = lane >> 2, tg = lane & 3;

    int mat = blockIdx.z;
    int m0 = blockIdx.x * 128;
    int n0 = blockIdx.y * 128;

    if (tid < 128) {
        sl[tid] = 0.f;
        wdec[tid] = __expf((float)(127-tid)*logf(GAMMA)) * g_ic[(m0+tid) & (SEQ-1)];
    }

    const float* X = (mat==0) ? xq : (mat==1 ? xk : xv);
    X += (size_t)m0*DIM;
    const __half* Wh = g_Wth + mat*DIM*DIM + (size_t)n0*DIM;
    const float* bias = (mat==0) ? bq : (mat==1 ? bk : bv);
    __half* OH = ((mat==0) ? g_Qh : (mat==1 ? g_Kh : g_Vh)) + (size_t)m0*DIM;
    __half* OL = ((mat==0) ? g_Ql : g_Kl) + (size_t)m0*DIM;

    uint32_t smb = smem_u32(sm);
    float acc[4][4][4] = {};
    float4 xr[4];

    #pragma unroll
    for (int l = 0; l < 4; l++) {
        int i = tid + l*256;
        int row = i >> 3, c4 = (i & 7)*4;
        xr[l] = *(const float4*)&X[(size_t)row*DIM + c4];
    }
    #pragma unroll
    for (int s = 0; s < 2; s++) {
        #pragma unroll
        for (int l = 0; l < 2; l++) {
            int i = tid + l*256;
            int row = i >> 2, c8 = (i & 3)*8;
            cpa(smb + P_W(s) + (row*PAD + c8)*2, &Wh[(size_t)row*DIM + s*32 + c8]);
        }
        CPA_COMMIT;
    }

    for (int st = 0; st < 8; st++) {
        if (st < 7) CPA_WAIT(1); else CPA_WAIT(0);
        char* xb = sm + P_X(st & 1);
        #pragma unroll
        for (int l = 0; l < 4; l++) {
            int i = tid + l*256;
            int row = i >> 3, c4 = (i & 7)*4;
            uint32_t l01, l23;
            uint32_t h01 = pack2(xr[l].x, xr[l].y, l01);
            uint32_t h23 = pack2(xr[l].z, xr[l].w, l23);
            *(uint2*)(xb + (row*PAD + c4)*2)         = make_uint2(h01, h23);
            *(uint2*)(xb + 10240 + (row*PAD + c4)*2) = make_uint2(l01, l23);
        }
        if (st < 7) {
            int kn = (st+1)*32;
            #pragma unroll
            for (int l = 0; l < 4; l++) {
                int i = tid + l*256;
                int row = i >> 3, c4 = (i & 7)*4;
                xr[l] = *(const float4*)&X[(size_t)row*DIM + kn + c4];
            }
        }
        __syncthreads();
        if (st + 2 < 8) {
            int kn = (st+2)*32;
            uint32_t wb = smb + P_W((st+2)%3);
            #pragma unroll
            for (int l = 0; l < 2; l++) {
                int i = tid + l*256;
                int row = i >> 2, c8 = (i & 3)*8;
                cpa(wb + (row*PAD + c8)*2, &Wh[(size_t)row*DIM + kn + c8]);
            }
            CPA_COMMIT;
        }
        uint32_t sXh = smb + P_X(st & 1), sXl = sXh + 10240;
        uint32_t sBh = smb + P_W(st % 3);
        #pragma unroll
        for (int ks = 0; ks < 32; ks += 16) {
            uint32_t ah[4][4], al[4][4];
            #pragma unroll
            for (int mf = 0; mf < 4; mf++) {
                ldsm4(ah[mf], addr_am(sXh, lane, wm*64 + mf*16, ks, PAD));
                ldsm4(al[mf], addr_am(sXl, lane, wm*64 + mf*16, ks, PAD));
            }
            uint32_t bh[2][4];
            #pragma unroll
            for (int p = 0; p < 2; p++)
                ldsm4(bh[p], addr_bn(sBh, lane, wn*32 + p*16, ks, PAD));
            #pragma unroll
            for (int nf = 0; nf < 4; nf++) {
                const uint32_t* pbh = &bh[nf>>1][(nf&1)*2];
                #pragma unroll
                for (int mf = 0; mf < 4; mf++) {
                    mma16816(acc[mf][nf], ah[mf], pbh);
                    mma16816(acc[mf][nf], al[mf], pbh);
                }
            }
        }
    }

    #pragma unroll
    for (int nf = 0; nf < 4; nf++) {
        int col = n0 + wn*32 + nf*8 + tg*2;
        float b0 = bias[col], b1 = bias[col+1];
        float s0 = 0.f, s1 = 0.f;
        #pragma unroll
        for (int mf = 0; mf < 4; mf++) {
            int row = wm*64 + mf*16 + gr;
            float v00 = acc[mf][nf][0] + b0, v01 = acc[mf][nf][1] + b1;
            float v10 = acc[mf][nf][2] + b0, v11 = acc[mf][nf][3] + b1;
            uint32_t lw0, lw1;
            uint32_t hw0 = pack2(v00, v01, lw0);
            uint32_t hw1 = pack2(v10, v11, lw1);
            *(uint32_t*)&OH[(size_t)row*DIM + col]     = hw0;
            *(uint32_t*)&OH[(size_t)(row+8)*DIM + col] = hw1;
            if (mat < 2) {
                *(uint32_t*)&OL[(size_t)row*DIM + col]     = lw0;
                *(uint32_t*)&OL[(size_t)(row+8)*DIM + col] = lw1;
            }
            if (mat == 1) {
                s0 += wdec[row]*v00 + wdec[row+8]*v10;
                s1 += wdec[row]*v01 + wdec[row+8]*v11;
            }
        }
        if (mat == 1) {
            int cl = wn*32 + nf*8 + tg*2;
            atomicAdd(&sl[cl], s0);
            atomicAdd(&sl[cl+1], s1);
        }
    }
    if (mat == 1) {
        __syncthreads();
        if (tid < 128) g_sloc[blockIdx.x*DIM + n0 + tid] = sl[tid];
    }
}

// ---------------- K2: fused S + dinv + T_local (per chunk) -----------------
// phase A ring: QH +0, QL +10240, KH +20480 per stage
#define S_BUF(s) ((s)*30720)
// phase T: wK hi/lo 128x136, V hi 128x136
#define TK_H 0
#define TK_L 34816
#define TV   69632
#define SM_KS 122880
__global__ void __launch_bounds__(512,1) k_mid() {
    extern __shared__ char sm[];
    __shared__ float rowg[CHK];
    __shared__ float cw[CHK];
    __shared__ float rsum[CHK];
    __shared__ float dv[CHK];
    __shared__ float sbd_s[DIM];
    int tid = threadIdx.x, lane = tid & 31, warp = tid >> 5;
    int gr = lane >> 2, tg = lane & 3;
    int wm = warp & 3, wn = warp >> 2;   // 4x4 warps
    int blk = blockIdx.x, b = blk >> 5, c = blk & 31, c0 = c*CHK;
    float lg = logf(GAMMA);
    uint32_t smb = smem_u32(sm);

    const __half *Qh = g_Qh + (size_t)(b*SEQ + c0)*DIM;
    const __half *Ql = g_Ql + (size_t)(b*SEQ + c0)*DIM;
    const __half *Kh = g_Kh + (size_t)(b*SEQ + c0)*DIM;
    const __half *Kl = g_Kl + (size_t)(b*SEQ + c0)*DIM;
    const __half *Vh = g_Vh + (size_t)(b*SEQ + c0)*DIM;

    // phase A prologue: stages 0..2
    {
        int row = tid >> 2, c8 = (tid & 3)*8;
        uint32_t so = (uint32_t)(row*PAD + c8)*2;
        #pragma unroll
        for (int s = 0; s < 3; s++) {
            size_t go = (size_t)row*DIM + s*32 + c8;
            uint32_t bb = smb + S_BUF(s);
            cpa(bb + so,         Qh + go);
            cpa(bb + 10240 + so, Ql + go);
            cpa(bb + 20480 + so, Kh + go);
            CPA_COMMIT;
        }
    }

    if (tid < CHK) {
        rowg[tid] = __expf((float)tid * lg);
        cw[tid]   = g_ic[c0 + tid]*INV16 * __expf(-(float)tid * lg);
        rsum[tid] = 0.f;
    }
    // fused spref: sbd for this chunk (batched loads, then serial combine)
    if (tid < DIM) {
        float v[NCH-1];
        #pragma unroll
        for (int c2 = 0; c2 < NCH-1; c2++)
            v[c2] = (c2 < c) ? g_sloc[(b*NCH + c2)*DIM + tid] : 0.f;
        float gC = __expf(128.f*lg);
        float s = 0.f;
        for (int c2 = 0; c2 < c; c2++) s = s*gC + v[c2];
        sbd_s[tid] = s;
    }
    __syncthreads();

    // cross-chunk row-sum term (overlaps prologue cp.async)
    {
        int row = tid >> 2, q = tid & 3;
        int dbase = q*64;
        size_t qp = (size_t)row*DIM + dbase;
        const float* sb = &sbd_s[dbase];
        float part = 0.f;
        #pragma unroll
        for (int d = 0; d < 64; d += 8) {
            float qf[8]; load8(qf, Qh + qp + d, Ql + qp + d);
            float4 s1 = *(const float4*)&sb[d], s2 = *(const float4*)&sb[d+4];
            part += qf[0]*s1.x + qf[1]*s1.y + qf[2]*s1.z + qf[3]*s1.w
                  + qf[4]*s2.x + qf[5]*s2.y + qf[6]*s2.z + qf[7]*s2.w;
        }
        atomicAdd(&rsum[row], part * __expf((float)(row+1)*lg) * INV16);
    }

    // ---- phase A: S = Q K^T, 2-pass ----
    float accA[2][4][4] = {};
    for (int st = 0; st < 8; st++) {
        if (st < 6) CPA_WAIT(2); else if (st == 6) CPA_WAIT(1); else CPA_WAIT(0);
        __syncthreads();
        if (st + 3 < 8) {
            int en = (st+3)*32;
            uint32_t bb = smb + S_BUF((st+3)&3);
            int row = tid >> 2, c8 = (tid & 3)*8;
            uint32_t so = (uint32_t)(row*PAD + c8)*2;
            size_t go = (size_t)row*DIM + en + c8;
            cpa(bb + so,         Qh + go);
            cpa(bb + 10240 + so, Ql + go);
            cpa(bb + 20480 + so, Kh + go);
            CPA_COMMIT;
        }
        uint32_t cb = smb + S_BUF(st & 3);
        #pragma unroll
        for (int ks = 0; ks < 32; ks += 16) {
            uint32_t ah[2][4], al[2][4];
            #pragma unroll
            for (int mf = 0; mf < 2; mf++) {
                ldsm4(ah[mf], addr_am(cb, lane, wm*32 + mf*16, ks, PAD));
                ldsm4(al[mf], addr_am(cb + 10240, lane, wm*32 + mf*16, ks, PAD));
            }
            uint32_t bh[2][4];
            #pragma unroll
            for (int p = 0; p < 2; p++)
                ldsm4(bh[p], addr_bn(cb + 20480, lane, wn*32 + p*16, ks, PAD));
            #pragma unroll
            for (int nf = 0; nf < 4; nf++) {
                const uint32_t* pbh = &bh[nf>>1][(nf&1)*2];
                #pragma unroll
                for (int mf = 0; mf < 2; mf++) {
                    mma16816(accA[mf][nf], ah[mf], pbh);
                    mma16816(accA[mf][nf], al[mf], pbh);
                }
            }
        }
    }

    // mask + decay, accumulate row sums
    #pragma unroll
    for (int mf = 0; mf < 2; mf++) {
        int i1 = wm*32 + mf*16 + gr, i2 = i1 + 8;
        float r1 = rowg[i1], r2 = rowg[i2];
        float rs1 = 0.f, rs2 = 0.f;
        #pragma unroll
        for (int nf = 0; nf < 4; nf++) {
            int j = wn*32 + nf*8 + tg*2;
            float cj0 = cw[j], cj1 = cw[j+1];
            accA[mf][nf][0] = (i1 >= j)   ? accA[mf][nf][0]*r1*cj0 : 0.f;
            accA[mf][nf][1] = (i1 >= j+1) ? accA[mf][nf][1]*r1*cj1 : 0.f;
            accA[mf][nf][2] = (i2 >= j)   ? accA[mf][nf][2]*r2*cj0 : 0.f;
            accA[mf][nf][3] = (i2 >= j+1) ? accA[mf][nf][3]*r2*cj1 : 0.f;
            rs1 += accA[mf][nf][0] + accA[mf][nf][1];
            rs2 += accA[mf][nf][2] + accA[mf][nf][3];
        }
        atomicAdd(&rsum[i1], rs1);
        atomicAdd(&rsum[i2], rs2);
    }
    __syncthreads();
    if (tid < CHK) dv[tid] = 1.0f / fmaxf(fabsf(rsum[tid]), 1.0f);
    __syncthreads();

    // S write (column dinv applied)
    #pragma unroll
    for (int mf = 0; mf < 2; mf++) {
        int i1 = wm*32 + mf*16 + gr, i2 = i1 + 8;
        #pragma unroll
        for (int nf = 0; nf < 4; nf++) {
            int j = wn*32 + nf*8 + tg*2;
            float dj0 = dv[j], dj1 = dv[j+1];
            uint32_t lw;
            uint32_t hw = pack2(accA[mf][nf][0]*dj0, accA[mf][nf][1]*dj1, lw);
            *(uint32_t*)&g_Sh[(size_t)(blk*CHK + i1)*CHK + j] = hw;
            *(uint32_t*)&g_Sl[(size_t)(blk*CHK + i1)*CHK + j] = lw;
            hw = pack2(accA[mf][nf][2]*dj0, accA[mf][nf][3]*dj1, lw);
            *(uint32_t*)&g_Sh[(size_t)(blk*CHK + i2)*CHK + j] = hw;
            *(uint32_t*)&g_Sl[(size_t)(blk*CHK + i2)*CHK + j] = lw;
        }
    }

    // ---- phase T: local T = (w.K)^T @ V, 4 tiles of 128x128 --------------
    // w2[j] = g^(127-j) * ic_j * INV16 * dinv_j = g^127 * cw[j] * dv[j]
    float g127 = rowg[127] ; // gamma^127
    for (int tile = 0; tile < 4; tile++) {
        int d1t = (tile >> 1)*128, d2t = (tile & 1)*128;
        __syncthreads();   // previous tile's smem reads done
        // V tile via cp.async
        #pragma unroll
        for (int l = 0; l < 4; l++) {
            int u = tid + l*512;
            int row = u >> 4, c8 = (u & 15)*8;
            cpa(smb + TV + (uint32_t)(row*136 + c8)*2, Vh + (size_t)row*DIM + d2t + c8);
        }
        CPA_COMMIT;
        // wK tile: reconstruct, scale, split
        #pragma unroll
        for (int l = 0; l < 4; l++) {
            int u = tid + l*512;
            int row = u >> 4, c8 = (u & 15)*8;
            size_t gp = (size_t)row*DIM + d1t + c8;
            float f[8]; load8(f, Kh + gp, Kl + gp);
            float w = g127 * cw[row] * dv[row];
            uint32_t hw[4], lw[4];
            #pragma unroll
            for (int i2 = 0; i2 < 4; i2++) hw[i2] = pack2(f[2*i2]*w, f[2*i2+1]*w, lw[i2]);
            *(uint4*)(sm + TK_H + (row*136 + c8)*2) = *(uint4*)hw;
            *(uint4*)(sm + TK_L + (row*136 + c8)*2) = *(uint4*)lw;
        }
        CPA_WAIT(0);
        __syncthreads();
        // MMA: [128 d1] x [128 d2] over j=128
        float accT[2][4][4] = {};
        for (int ks = 0; ks < 128; ks += 16) {
            uint32_t ah[2][4], al[2][4];
            #pragma unroll
            for (int mf = 0; mf < 2; mf++) {
                ldsm4t(ah[mf], aaddr_t(smb + TK_H, lane, wm*32 + mf*16, ks, 136));
                ldsm4t(al[mf], aaddr_t(smb + TK_L, lane, wm*32 + mf*16, ks, 136));
            }
            uint32_t bh[2][4];
            #pragma unroll
            for (int p = 0; p < 2; p++)
                ldsm4t(bh[p], baddr(smb + TV, lane, ks, wn*32 + p*16, 136));
            #pragma unroll
            for (int nf = 0; nf < 4; nf++) {
                const uint32_t* pb = &bh[nf>>1][(nf&1)*2];
                #pragma unroll
                for (int mf = 0; mf < 2; mf++) {
                    mma16816(accT[mf][nf], ah[mf], pb);
                    mma16816(accT[mf][nf], al[mf], pb);
                }
            }
        }
        // store local T fp16
        #pragma unroll
        for (int mf = 0; mf < 2; mf++) {
            int d1 = d1t + wm*32 + mf*16 + gr;
            #pragma unroll
            for (int nf = 0; nf < 4; nf++) {
                int d2 = d2t + wn*32 + nf*8 + tg*2;
                __half2 p0 = __floats2half2_rn(accT[mf][nf][0], accT[mf][nf][1]);
                __half2 p1 = __floats2half2_rn(accT[mf][nf][2], accT[mf][nf][3]);
                *(uint32_t*)&g_Th[((size_t)blk*DIM + d1)*DIM + d2]     = *(uint32_t*)&p0;
                *(uint32_t*)&g_Th[((size_t)blk*DIM + d1 + 8)*DIM + d2] = *(uint32_t*)&p1;
            }
        }
    }
}

// ---------------- K6: in-place prefix of T (fp16, half2-vectorized) -------
__global__ void k_tpref() {   // grid 512, 256 threads; 2 elements per thread
    int idx = blockIdx.x*256 + threadIdx.x;   // half2 index, [0, BB*32768)
    int b   = idx >> 15;
    int off = (idx & 32767)*2;
    float2 v[NCH];
    #pragma unroll
    for (int c = 0; c < NCH; c++) {
        uint32_t w = *(const uint32_t*)&g_Th[(((size_t)(b*NCH + c)) << 16) + off];
        v[c] = __half22float2(*(__half2*)&w);
    }
    float gC = __expf(128.f*logf(GAMMA));
    float t0 = 0.f, t1 = 0.f;
    #pragma unroll
    for (int c = 0; c < NCH; c++) {
        __half2 p = __floats2half2_rn(t0, t1);
        *(uint32_t*)&g_Th[(((size_t)(b*NCH + c)) << 16) + off] = *(uint32_t*)&p;
        t0 = t0*gC + v[c].x;
        t1 = t1*gC + v[c].y;
    }
}

// ---------------- K7b: out = S@V + (g^{i+1} Q)@T — 2-pass -----------------
#define B1_S(s) ((s)*37376)             // SH +0, SL +10240, VH +20480 (16896)
#define B2_Q(p) ((p)*20480)             // QH +0, QL +10240
#define B2_T(s) (40960 + (s)*16896)     // TH only
#define SM_KB 112128
__global__ void __launch_bounds__(512,1) k_B(float* __restrict__ out) {
    extern __shared__ char sm[];
    __shared__ float rowGn[CHK];
    int tid = threadIdx.x, lane = tid & 31, warp = tid >> 5;
    int gr = lane >> 2, tg = lane & 3;
    int wm = warp & 3, wn = warp >> 2;   // 4x4 warps, 32(m) x 64(n)
    int blk = blockIdx.x, b = blk >> 5, c = blk & 31, c0 = c*CHK;
    uint32_t smb = smem_u32(sm);

    const __half *Sh = g_Sh + (size_t)blk*CHK*CHK;
    const __half *Sl = g_Sl + (size_t)blk*CHK*CHK;
    const __half *Vh = g_Vh + (size_t)(b*SEQ + c0)*DIM;
    const __half *Qh = g_Qh + (size_t)(b*SEQ + c0)*DIM;
    const __half *Ql = g_Ql + (size_t)(b*SEQ + c0)*DIM;
    const __half *Th = g_Th + (size_t)blk*65536;

    if (tid < CHK) rowGn[tid] = __expf((float)(tid+1) * logf(GAMMA));

    #pragma unroll
    for (int s = 0; s < 2; s++) {
        uint32_t bb = smb + B1_S(s);
        {
            int row = tid >> 2, c8 = (tid & 3)*8;
            uint32_t so = (uint32_t)(row*PAD + c8)*2;
            cpa(bb + so,         Sh + (size_t)row*CHK + s*32 + c8);
            cpa(bb + 10240 + so, Sl + (size_t)row*CHK + s*32 + c8);
        }
        #pragma unroll
        for (int l = 0; l < 2; l++) {
            int u = tid + l*512;
            int row = u >> 5, c8 = (u & 31)*8;
            cpa(bb + 20480 + (uint32_t)(row*264 + c8)*2, Vh + (size_t)(s*32+row)*DIM + c8);
        }
        CPA_COMMIT;
    }
    __syncthreads();

    float acc[2][8][4] = {};

    // ---- B1: S @ V, 4 stages, 3-ring ----
    for (int st = 0; st < 4; st++) {
        if (st < 3) CPA_WAIT(1); else CPA_WAIT(0);
        __syncthreads();
        if (st + 2 < 4) {
            int kn = (st+2)*32;
            uint32_t bb = smb + B1_S((st+2)%3);
            {
                int row = tid >> 2, c8 = (tid & 3)*8;
                uint32_t so = (uint32_t)(row*PAD + c8)*2;
                cpa(bb + so,         Sh + (size_t)row*CHK + kn + c8);
                cpa(bb + 10240 + so, Sl + (size_t)row*CHK + kn + c8);
            }
            #pragma unroll
            for (int l = 0; l < 2; l++) {
                int u = tid + l*512;
                int row = u >> 5, c8 = (u & 31)*8;
                cpa(bb + 20480 + (uint32_t)(row*264 + c8)*2, Vh + (size_t)(kn+row)*DIM + c8);
            }
            CPA_COMMIT;
        }
        uint32_t cb = smb + B1_S(st % 3);
        #pragma unroll
        for (int ks = 0; ks < 32; ks += 16) {
            uint32_t ah[2][4], al[2][4];
            #pragma unroll
            for (int mf = 0; mf < 2; mf++) {
                ldsm4(ah[mf], addr_am(cb, lane, wm*32 + mf*16, ks, PAD));
                ldsm4(al[mf], addr_am(cb + 10240, lane, wm*32 + mf*16, ks, PAD));
            }
            #pragma unroll
            for (int nfp = 0; nfp < 4; nfp++) {
                uint32_t bh[4];
                ldsm4t(bh, baddr(cb + 20480, lane, ks, wn*64 + nfp*16, 264));
                #pragma unroll
                for (int mf = 0; mf < 2; mf++) {
                    mma16816(acc[mf][2*nfp],   ah[mf], bh);
                    mma16816(acc[mf][2*nfp+1], ah[mf], bh+2);
                    mma16816(acc[mf][2*nfp],   al[mf], bh);
                    mma16816(acc[mf][2*nfp+1], al[mf], bh+2);
                }
            }
        }
    }
    __syncthreads();   // B1 reads done before B2 overwrites buffers

    // ---- B2: (g^{i+1} Q) @ T_prefix, 8 stages, 3-ring T + 2-buf STS Q ----
    uint4 qhr, qlr;
    {
        int row = tid >> 2, c8 = (tid & 3)*8;
        qhr = *(const uint4*)(Qh + (size_t)row*DIM + c8);
        qlr = *(const uint4*)(Ql + (size_t)row*DIM + c8);
    }
    #pragma unroll
    for (int s = 0; s < 2; s++) {
        uint32_t bb = smb + B2_T(s);
        #pragma unroll
        for (int l = 0; l < 2; l++) {
            int u = tid + l*512;
            int row = u >> 5, c8 = (u & 31)*8;
            cpa(bb + (uint32_t)(row*264 + c8)*2, Th + (size_t)(s*32+row)*DIM + c8);
        }
        CPA_COMMIT;
    }

    for (int st = 0; st < 8; st++) {
        if (st < 7) CPA_WAIT(1); else CPA_WAIT(0);
        char* qb = sm + B2_Q(st & 1);
        {
            int row = tid >> 2, c8 = (tid & 3)*8;
            float f[8]; load8r(f, qhr, qlr);
            float rG = rowGn[row];
            uint32_t hw[4], lw[4];
            #pragma unroll
            for (int i2 = 0; i2 < 4; i2++) hw[i2] = pack2(f[2*i2]*rG, f[2*i2+1]*rG, lw[i2]);
            *(uint4*)(qb + (row*PAD + c8)*2)         = *(uint4*)hw;
            *(uint4*)(qb + 10240 + (row*PAD + c8)*2) = *(uint4*)lw;
        }
        if (st < 7) {
            int en = (st+1)*32;
            int row = tid >> 2, c8 = (tid & 3)*8;
            qhr = *(const uint4*)(Qh + (size_t)row*DIM + en + c8);
            qlr = *(const uint4*)(Ql + (size_t)row*DIM + en + c8);
        }
        __syncthreads();
        if (st + 2 < 8) {
            int en = (st+2)*32;
            uint32_t bb = smb + B2_T((st+2)%3);
            #pragma unroll
            for (int l = 0; l < 2; l++) {
                int u = tid + l*512;
                int row = u >> 5, c8 = (u & 31)*8;
                cpa(bb + (uint32_t)(row*264 + c8)*2, Th + (size_t)(en+row)*DIM + c8);
            }
            CPA_COMMIT;
        }
        uint32_t ab = smb + B2_Q(st & 1);
        uint32_t bb = smb + B2_T(st % 3);
        #pragma unroll
        for (int ks = 0; ks < 32; ks += 16) {
            uint32_t ah[2][4], al[2][4];
            #pragma unroll
            for (int mf = 0; mf < 2; mf++) {
                ldsm4(ah[mf], addr_am(ab, lane, wm*32 + mf*16, ks, PAD));
                ldsm4(al[mf], addr_am(ab + 10240, lane, wm*32 + mf*16, ks, PAD));
            }
            #pragma unroll
            for (int nfp = 0; nfp < 4; nfp++) {
                uint32_t bh[4];
                ldsm4t(bh, baddr(bb, lane, ks, wn*64 + nfp*16, 264));
                #pragma unroll
                for (int mf = 0; mf < 2; mf++) {
                    mma16816(acc[mf][2*nfp],   ah[mf], bh);
                    mma16816(acc[mf][2*nfp+1], ah[mf], bh+2);
                    mma16816(acc[mf][2*nfp],   al[mf], bh);
                    mma16816(acc[mf][2*nfp+1], al[mf], bh+2);
                }
            }
        }
    }

    #pragma unroll
    for (int mf = 0; mf < 2; mf++) {
        int i1 = wm*32 + mf*16 + gr;
        #pragma unroll
        for (int nf = 0; nf < 8; nf++) {
            int n = wn*64 + nf*8 + tg*2;
            *(float2*)&out[(size_t)(b*SEQ + c0 + i1)*DIM + n]     = make_float2(acc[mf][nf][0], acc[mf][nf][1]);
            *(float2*)&out[(size_t)(b*SEQ + c0 + i1 + 8)*DIM + n] = make_float2(acc[mf][nf][2], acc[mf][nf][3]);
        }
    }
}

// -------------------------------------------------------------------------
extern "C" void kernel_launch(void* const* d_in, const int* in_sizes, int n_in,
                              void* d_out, int out_size) {
    const float* xq = (const float*)d_in[0];
    const float* xk = (const float*)d_in[1];
    const float* xv = (const float*)d_in[2];
    const float* Wq = (const float*)d_in[3];
    const float* bq = (const float*)d_in[4];
    const float* Wk = (const float*)d_in[5];
    const float* bk = (const float*)d_in[6];
    const float* Wv = (const float*)d_in[7];
    const float* bv = (const float*)d_in[8];
    float* out = (float*)d_out;

    static int once = 0;
    if (!once) {
        cudaFuncSetAttribute(k_proj_mma, cudaFuncAttributeMaxDynamicSharedMemorySize, SM_PROJ);
        cudaFuncSetAttribute(k_mid,      cudaFuncAttributeMaxDynamicSharedMemorySize, SM_KS);
        cudaFuncSetAttribute(k_B,        cudaFuncAttributeMaxDynamicSharedMemorySize, SM_KB);
        once = 1;
    }

    k_prep  <<<dim3(DIM, 3), 256>>>(Wq, Wk, Wv);
    k_proj_mma<<<dim3(ROWS_TOT/128, DIM/128, 3), 256, SM_PROJ>>>(xq, xk, xv, bq, bk, bv);
    k_mid   <<<BB*NCH, 512, SM_KS>>>();
    k_tpref <<<512, 256>>>();
    k_B     <<<BB*NCH, 512, SM_KB>>>(out);
}

// round 17
// speedup vs baseline: 1.2887x; 1.0770x over previous
#include <cuda_runtime.h>
#include <cuda_fp16.h>
#include <math.h>
#include <stdint.h>

#define BB 4
#define SEQ 4096
#define DIM 256
#define CHK 128
#define NCH (SEQ/CHK)      // 32
#define GAMMA 0.9865f
#define INV16 0.0625f
#define ROWS_TOT (BB*SEQ)  // 16384
#define PAD 40

// ---------------- scratch ----------------
__device__ float g_ic[SEQ];
__device__ float g_sloc[BB*NCH*DIM];
__device__ __half g_Th[(size_t)BB*NCH*DIM*DIM];   // local T, then prefix in place

__device__ __half g_Qh[BB*SEQ*DIM];
__device__ __half g_Ql[BB*SEQ*DIM];
__device__ __half g_Kh[BB*SEQ*DIM];
__device__ __half g_Kl[BB*SEQ*DIM];
__device__ __half g_Vh[BB*SEQ*DIM];

__device__ __half g_Sh[(size_t)BB*SEQ*CHK];       // masked scores, hi only

__device__ __half g_Wth[3*DIM*DIM];               // W^T [n][k], hi only

// ======================= helpers =========================================
__device__ __forceinline__ uint32_t smem_u32(const void* p) {
    uint32_t a;
    asm("{ .reg .u64 t; cvta.to.shared.u64 t, %1; cvt.u32.u64 %0, t; }" : "=r"(a) : "l"(p));
    return a;
}
__device__ __forceinline__ void cpa(uint32_t d, const void* s) {
    asm volatile("cp.async.cg.shared.global [%0], [%1], 16;" :: "r"(d), "l"(s));
}
#define CPA_COMMIT asm volatile("cp.async.commit_group;" ::: "memory")
#define CPA_WAIT(n) asm volatile("cp.async.wait_group %0;" :: "n"(n) : "memory")

__device__ __forceinline__ void mma16816(float* c, const uint32_t* a, const uint32_t* b) {
    asm volatile(
        "mma.sync.aligned.m16n8k16.row.col.f32.f16.f16.f32 "
        "{%0,%1,%2,%3}, {%4,%5,%6,%7}, {%8,%9}, {%0,%1,%2,%3};"
        : "+f"(c[0]), "+f"(c[1]), "+f"(c[2]), "+f"(c[3])
        : "r"(a[0]), "r"(a[1]), "r"(a[2]), "r"(a[3]), "r"(b[0]), "r"(b[1]));
}
__device__ __forceinline__ void ldsm4(uint32_t* r, uint32_t a) {
    asm volatile("ldmatrix.sync.aligned.m8n8.x4.shared.b16 {%0,%1,%2,%3}, [%4];"
        : "=r"(r[0]), "=r"(r[1]), "=r"(r[2]), "=r"(r[3]) : "r"(a));
}
__device__ __forceinline__ void ldsm4t(uint32_t* r, uint32_t a) {
    asm volatile("ldmatrix.sync.aligned.m8n8.x4.trans.shared.b16 {%0,%1,%2,%3}, [%4];"
        : "=r"(r[0]), "=r"(r[1]), "=r"(r[2]), "=r"(r[3]) : "r"(a));
}
__device__ __forceinline__ uint32_t addr_am(uint32_t base, int lane, int m0, int k0, int L) {
    int row = m0 + (lane & 7) + ((lane >> 3) & 1)*8;
    int col = k0 + ((lane >> 4) & 1)*8;
    return base + (uint32_t)(row*L + col)*2;
}
__device__ __forceinline__ uint32_t addr_bn(uint32_t base, int lane, int n0, int k0, int L) {
    int row = n0 + (lane & 7) + ((lane >> 4) & 1)*8;
    int col = k0 + ((lane >> 3) & 1)*8;
    return base + (uint32_t)(row*L + col)*2;
}
__device__ __forceinline__ uint32_t baddr(uint32_t base, int lane, int k0, int n0, int L) {
    int row = k0 + (lane & 7) + ((lane >> 3) & 1)*8;
    int col = n0 + ((lane >> 4) & 1)*8;
    return base + (uint32_t)(row*L + col)*2;
}
__device__ __forceinline__ uint32_t aaddr_t(uint32_t base, int lane, int m0, int k0, int L) {
    int row = k0 + (lane & 7) + ((lane >> 4) & 1)*8;
    int col = m0 + ((lane >> 3) & 1)*8;
    return base + (uint32_t)(row*L + col)*2;
}
__device__ __forceinline__ uint32_t pack2(float a, float b, uint32_t& lo) {
    __half2 hh = __floats2half2_rn(a, b);
    float2 bk = __half22float2(hh);
    __half2 ll = __floats2half2_rn(a - bk.x, b - bk.y);
    lo = *(uint32_t*)&ll;
    return *(uint32_t*)&hh;
}
__device__ __forceinline__ void load8(float* f, const __half* h, const __half* l) {
    uint4 hv = *(const uint4*)h, lv = *(const uint4*)l;
    const __half2* hp = (const __half2*)&hv;
    const __half2* lp = (const __half2*)&lv;
    #pragma unroll
    for (int i = 0; i < 4; i++) {
        float2 a = __half22float2(hp[i]), bq = __half22float2(lp[i]);
        f[2*i] = a.x + bq.x; f[2*i+1] = a.y + bq.y;
    }
}
__device__ __forceinline__ void load8r(float* f, uint4 hv, uint4 lv) {
    const __half2* hp = (const __half2*)&hv;
    const __half2* lp = (const __half2*)&lv;
    #pragma unroll
    for (int i = 0; i < 4; i++) {
        float2 a = __half22float2(hp[i]), bq = __half22float2(lp[i]);
        f[2*i] = a.x + bq.x; f[2*i+1] = a.y + bq.y;
    }
}

// ---------------- K0: W split + ic ---------------------------------------
__global__ void k_prep(const float* __restrict__ Wq, const float* __restrict__ Wk,
                       const float* __restrict__ Wv) {
    int mat = blockIdx.y;
    const float* W = (mat==0) ? Wq : (mat==1 ? Wk : Wv);
    int k = blockIdx.x, n = threadIdx.x;
    float w = W[k*DIM + n];
    g_Wth[mat*DIM*DIM + n*DIM + k] = __float2half_rn(w);
    if (mat == 0 && k < 16) {
        int j = k*256 + n;
        float lg = logf(GAMMA);
        float gp = expf((float)(j+1)*lg);
        g_ic[j] = rsqrtf((1.0f - gp)/(1.0f - GAMMA));
    }
}

// ---------------- K1: projection — 2-pass fp16 (Wh only), 3-stage ring ----
#define P_X(p) ((p)*20480)              // XH +0, XL +10240
#define P_W(s) (40960 + (s)*10240)      // WH only
#define SM_PROJ 71680
__global__ void __launch_bounds__(256,2) k_proj_mma(
    const float* __restrict__ xq, const float* __restrict__ xk, const float* __restrict__ xv,
    const float* __restrict__ bq, const float* __restrict__ bk, const float* __restrict__ bv)
{
    extern __shared__ char sm[];
    __shared__ float sl[128];
    __shared__ float wdec[128];

    int tid = threadIdx.x;
    int warp = tid >> 5, lane = tid & 31;
    int wm = warp & 1, wn = warp >> 1;
    int gr = lane >> 2, tg = lane & 3;

    int mat = blockIdx.z;
    int m0 = blockIdx.x * 128;
    int n0 = blockIdx.y * 128;

    if (tid < 128) {
        sl[tid] = 0.f;
        wdec[tid] = __expf((float)(127-tid)*logf(GAMMA)) * g_ic[(m0+tid) & (SEQ-1)];
    }

    const float* X = (mat==0) ? xq : (mat==1 ? xk : xv);
    X += (size_t)m0*DIM;
    const __half* Wh = g_Wth + mat*DIM*DIM + (size_t)n0*DIM;
    const float* bias = (mat==0) ? bq : (mat==1 ? bk : bv);
    __half* OH = ((mat==0) ? g_Qh : (mat==1 ? g_Kh : g_Vh)) + (size_t)m0*DIM;
    __half* OL = ((mat==0) ? g_Ql : g_Kl) + (size_t)m0*DIM;

    uint32_t smb = smem_u32(sm);
    float acc[4][4][4] = {};
    float4 xr[4];

    #pragma unroll
    for (int l = 0; l < 4; l++) {
        int i = tid + l*256;
        int row = i >> 3, c4 = (i & 7)*4;
        xr[l] = *(const float4*)&X[(size_t)row*DIM + c4];
    }
    #pragma unroll
    for (int s = 0; s < 2; s++) {
        #pragma unroll
        for (int l = 0; l < 2; l++) {
            int i = tid + l*256;
            int row = i >> 2, c8 = (i & 3)*8;
            cpa(smb + P_W(s) + (row*PAD + c8)*2, &Wh[(size_t)row*DIM + s*32 + c8]);
        }
        CPA_COMMIT;
    }

    for (int st = 0; st < 8; st++) {
        if (st < 7) CPA_WAIT(1); else CPA_WAIT(0);
        char* xb = sm + P_X(st & 1);
        #pragma unroll
        for (int l = 0; l < 4; l++) {
            int i = tid + l*256;
            int row = i >> 3, c4 = (i & 7)*4;
            uint32_t l01, l23;
            uint32_t h01 = pack2(xr[l].x, xr[l].y, l01);
            uint32_t h23 = pack2(xr[l].z, xr[l].w, l23);
            *(uint2*)(xb + (row*PAD + c4)*2)         = make_uint2(h01, h23);
            *(uint2*)(xb + 10240 + (row*PAD + c4)*2) = make_uint2(l01, l23);
        }
        if (st < 7) {
            int kn = (st+1)*32;
            #pragma unroll
            for (int l = 0; l < 4; l++) {
                int i = tid + l*256;
                int row = i >> 3, c4 = (i & 7)*4;
                xr[l] = *(const float4*)&X[(size_t)row*DIM + kn + c4];
            }
        }
        __syncthreads();
        if (st + 2 < 8) {
            int kn = (st+2)*32;
            uint32_t wb = smb + P_W((st+2)%3);
            #pragma unroll
            for (int l = 0; l < 2; l++) {
                int i = tid + l*256;
                int row = i >> 2, c8 = (i & 3)*8;
                cpa(wb + (row*PAD + c8)*2, &Wh[(size_t)row*DIM + kn + c8]);
            }
            CPA_COMMIT;
        }
        uint32_t sXh = smb + P_X(st & 1), sXl = sXh + 10240;
        uint32_t sBh = smb + P_W(st % 3);
        #pragma unroll
        for (int ks = 0; ks < 32; ks += 16) {
            uint32_t ah[4][4], al[4][4];
            #pragma unroll
            for (int mf = 0; mf < 4; mf++) {
                ldsm4(ah[mf], addr_am(sXh, lane, wm*64 + mf*16, ks, PAD));
                ldsm4(al[mf], addr_am(sXl, lane, wm*64 + mf*16, ks, PAD));
            }
            uint32_t bh[2][4];
            #pragma unroll
            for (int p = 0; p < 2; p++)
                ldsm4(bh[p], addr_bn(sBh, lane, wn*32 + p*16, ks, PAD));
            #pragma unroll
            for (int nf = 0; nf < 4; nf++) {
                const uint32_t* pbh = &bh[nf>>1][(nf&1)*2];
                #pragma unroll
                for (int mf = 0; mf < 4; mf++) {
                    mma16816(acc[mf][nf], ah[mf], pbh);
                    mma16816(acc[mf][nf], al[mf], pbh);
                }
            }
        }
    }

    #pragma unroll
    for (int nf = 0; nf < 4; nf++) {
        int col = n0 + wn*32 + nf*8 + tg*2;
        float b0 = bias[col], b1 = bias[col+1];
        float s0 = 0.f, s1 = 0.f;
        #pragma unroll
        for (int mf = 0; mf < 4; mf++) {
            int row = wm*64 + mf*16 + gr;
            float v00 = acc[mf][nf][0] + b0, v01 = acc[mf][nf][1] + b1;
            float v10 = acc[mf][nf][2] + b0, v11 = acc[mf][nf][3] + b1;
            uint32_t lw0, lw1;
            uint32_t hw0 = pack2(v00, v01, lw0);
            uint32_t hw1 = pack2(v10, v11, lw1);
            *(uint32_t*)&OH[(size_t)row*DIM + col]     = hw0;
            *(uint32_t*)&OH[(size_t)(row+8)*DIM + col] = hw1;
            if (mat < 2) {
                *(uint32_t*)&OL[(size_t)row*DIM + col]     = lw0;
                *(uint32_t*)&OL[(size_t)(row+8)*DIM + col] = lw1;
            }
            if (mat == 1) {
                s0 += wdec[row]*v00 + wdec[row+8]*v10;
                s1 += wdec[row]*v01 + wdec[row+8]*v11;
            }
        }
        if (mat == 1) {
            int cl = wn*32 + nf*8 + tg*2;
            atomicAdd(&sl[cl], s0);
            atomicAdd(&sl[cl+1], s1);
        }
    }
    if (mat == 1) {
        __syncthreads();
        if (tid < 128) g_sloc[blockIdx.x*DIM + n0 + tid] = sl[tid];
    }
}

// ---------------- K2: fused S + dinv + T_local (per chunk) -----------------
#define S_BUF(s) ((s)*30720)        // QH +0, QL +10240, KH +20480
#define TK_H 0
#define TV   34816
#define SM_KS 122880
__global__ void __launch_bounds__(512,1) k_mid() {
    extern __shared__ char sm[];
    __shared__ float rowg[CHK];
    __shared__ float cw[CHK];
    __shared__ float rsum[CHK];
    __shared__ float dv[CHK];
    __shared__ float sbd_s[DIM];
    int tid = threadIdx.x, lane = tid & 31, warp = tid >> 5;
    int gr = lane >> 2, tg = lane & 3;
    int wm = warp & 3, wn = warp >> 2;   // 4x4 warps
    int blk = blockIdx.x, b = blk >> 5, c = blk & 31, c0 = c*CHK;
    float lg = logf(GAMMA);
    uint32_t smb = smem_u32(sm);

    const __half *Qh = g_Qh + (size_t)(b*SEQ + c0)*DIM;
    const __half *Ql = g_Ql + (size_t)(b*SEQ + c0)*DIM;
    const __half *Kh = g_Kh + (size_t)(b*SEQ + c0)*DIM;
    const __half *Kl = g_Kl + (size_t)(b*SEQ + c0)*DIM;
    const __half *Vh = g_Vh + (size_t)(b*SEQ + c0)*DIM;

    // phase A prologue: stages 0..2
    {
        int row = tid >> 2, c8 = (tid & 3)*8;
        uint32_t so = (uint32_t)(row*PAD + c8)*2;
        #pragma unroll
        for (int s = 0; s < 3; s++) {
            size_t go = (size_t)row*DIM + s*32 + c8;
            uint32_t bb = smb + S_BUF(s);
            cpa(bb + so,         Qh + go);
            cpa(bb + 10240 + so, Ql + go);
            cpa(bb + 20480 + so, Kh + go);
            CPA_COMMIT;
        }
    }

    if (tid < CHK) {
        rowg[tid] = __expf((float)tid * lg);
        cw[tid]   = g_ic[c0 + tid]*INV16 * __expf(-(float)tid * lg);
        rsum[tid] = 0.f;
    }
    // fused spref: sbd for this chunk (batched loads, then serial combine)
    if (tid < DIM) {
        float v[NCH-1];
        #pragma unroll
        for (int c2 = 0; c2 < NCH-1; c2++)
            v[c2] = (c2 < c) ? g_sloc[(b*NCH + c2)*DIM + tid] : 0.f;
        float gC = __expf(128.f*lg);
        float s = 0.f;
        for (int c2 = 0; c2 < c; c2++) s = s*gC + v[c2];
        sbd_s[tid] = s;
    }
    __syncthreads();

    // cross-chunk row-sum term (overlaps prologue cp.async)
    {
        int row = tid >> 2, q = tid & 3;
        int dbase = q*64;
        size_t qp = (size_t)row*DIM + dbase;
        const float* sb = &sbd_s[dbase];
        float part = 0.f;
        #pragma unroll
        for (int d = 0; d < 64; d += 8) {
            float qf[8]; load8(qf, Qh + qp + d, Ql + qp + d);
            float4 s1 = *(const float4*)&sb[d], s2 = *(const float4*)&sb[d+4];
            part += qf[0]*s1.x + qf[1]*s1.y + qf[2]*s1.z + qf[3]*s1.w
                  + qf[4]*s2.x + qf[5]*s2.y + qf[6]*s2.z + qf[7]*s2.w;
        }
        atomicAdd(&rsum[row], part * __expf((float)(row+1)*lg) * INV16);
    }

    // ---- phase A: S = Q K^T, 2-pass ----
    float accA[2][4][4] = {};
    for (int st = 0; st < 8; st++) {
        if (st < 6) CPA_WAIT(2); else if (st == 6) CPA_WAIT(1); else CPA_WAIT(0);
        __syncthreads();
        if (st + 3 < 8) {
            int en = (st+3)*32;
            uint32_t bb = smb + S_BUF((st+3)&3);
            int row = tid >> 2, c8 = (tid & 3)*8;
            uint32_t so = (uint32_t)(row*PAD + c8)*2;
            size_t go = (size_t)row*DIM + en + c8;
            cpa(bb + so,         Qh + go);
            cpa(bb + 10240 + so, Ql + go);
            cpa(bb + 20480 + so, Kh + go);
            CPA_COMMIT;
        }
        uint32_t cb = smb + S_BUF(st & 3);
        #pragma unroll
        for (int ks = 0; ks < 32; ks += 16) {
            uint32_t ah[2][4], al[2][4];
            #pragma unroll
            for (int mf = 0; mf < 2; mf++) {
                ldsm4(ah[mf], addr_am(cb, lane, wm*32 + mf*16, ks, PAD));
                ldsm4(al[mf], addr_am(cb + 10240, lane, wm*32 + mf*16, ks, PAD));
            }
            uint32_t bh[2][4];
            #pragma unroll
            for (int p = 0; p < 2; p++)
                ldsm4(bh[p], addr_bn(cb + 20480, lane, wn*32 + p*16, ks, PAD));
            #pragma unroll
            for (int nf = 0; nf < 4; nf++) {
                const uint32_t* pbh = &bh[nf>>1][(nf&1)*2];
                #pragma unroll
                for (int mf = 0; mf < 2; mf++) {
                    mma16816(accA[mf][nf], ah[mf], pbh);
                    mma16816(accA[mf][nf], al[mf], pbh);
                }
            }
        }
    }

    // mask + decay, accumulate row sums
    #pragma unroll
    for (int mf = 0; mf < 2; mf++) {
        int i1 = wm*32 + mf*16 + gr, i2 = i1 + 8;
        float r1 = rowg[i1], r2 = rowg[i2];
        float rs1 = 0.f, rs2 = 0.f;
        #pragma unroll
        for (int nf = 0; nf < 4; nf++) {
            int j = wn*32 + nf*8 + tg*2;
            float cj0 = cw[j], cj1 = cw[j+1];
            accA[mf][nf][0] = (i1 >= j)   ? accA[mf][nf][0]*r1*cj0 : 0.f;
            accA[mf][nf][1] = (i1 >= j+1) ? accA[mf][nf][1]*r1*cj1 : 0.f;
            accA[mf][nf][2] = (i2 >= j)   ? accA[mf][nf][2]*r2*cj0 : 0.f;
            accA[mf][nf][3] = (i2 >= j+1) ? accA[mf][nf][3]*r2*cj1 : 0.f;
            rs1 += accA[mf][nf][0] + accA[mf][nf][1];
            rs2 += accA[mf][nf][2] + accA[mf][nf][3];
        }
        atomicAdd(&rsum[i1], rs1);
        atomicAdd(&rsum[i2], rs2);
    }
    __syncthreads();
    if (tid < CHK) dv[tid] = 1.0f / fmaxf(fabsf(rsum[tid]), 1.0f);
    __syncthreads();

    // S write, hi only
    #pragma unroll
    for (int mf = 0; mf < 2; mf++) {
        int i1 = wm*32 + mf*16 + gr, i2 = i1 + 8;
        #pragma unroll
        for (int nf = 0; nf < 4; nf++) {
            int j = wn*32 + nf*8 + tg*2;
            float dj0 = dv[j], dj1 = dv[j+1];
            __half2 h1 = __floats2half2_rn(accA[mf][nf][0]*dj0, accA[mf][nf][1]*dj1);
            __half2 h2 = __floats2half2_rn(accA[mf][nf][2]*dj0, accA[mf][nf][3]*dj1);
            *(uint32_t*)&g_Sh[(size_t)(blk*CHK + i1)*CHK + j] = *(uint32_t*)&h1;
            *(uint32_t*)&g_Sh[(size_t)(blk*CHK + i2)*CHK + j] = *(uint32_t*)&h2;
        }
    }

    // ---- phase T: local T = (w.K)^T @ V, 4 tiles, hi-only single-pass ----
    float g127 = rowg[127];
    for (int tile = 0; tile < 4; tile++) {
        int d1t = (tile >> 1)*128, d2t = (tile & 1)*128;
        __syncthreads();
        #pragma unroll
        for (int l = 0; l < 4; l++) {
            int u = tid + l*512;
            int row = u >> 4, c8 = (u & 15)*8;
            cpa(smb + TV + (uint32_t)(row*136 + c8)*2, Vh + (size_t)row*DIM + d2t + c8);
        }
        CPA_COMMIT;
        // wK tile: reconstruct, scale, hi-only store
        #pragma unroll
        for (int l = 0; l < 4; l++) {
            int u = tid + l*512;
            int row = u >> 4, c8 = (u & 15)*8;
            size_t gp = (size_t)row*DIM + d1t + c8;
            float f[8]; load8(f, Kh + gp, Kl + gp);
            float w = g127 * cw[row] * dv[row];
            uint32_t hw[4];
            #pragma unroll
            for (int i2 = 0; i2 < 4; i2++) {
                __half2 h = __floats2half2_rn(f[2*i2]*w, f[2*i2+1]*w);
                hw[i2] = *(uint32_t*)&h;
            }
            *(uint4*)(sm + TK_H + (row*136 + c8)*2) = *(uint4*)hw;
        }
        CPA_WAIT(0);
        __syncthreads();
        float accT[2][4][4] = {};
        for (int ks = 0; ks < 128; ks += 16) {
            uint32_t ah[2][4];
            #pragma unroll
            for (int mf = 0; mf < 2; mf++)
                ldsm4t(ah[mf], aaddr_t(smb + TK_H, lane, wm*32 + mf*16, ks, 136));
            uint32_t bh[2][4];
            #pragma unroll
            for (int p = 0; p < 2; p++)
                ldsm4t(bh[p], baddr(smb + TV, lane, ks, wn*32 + p*16, 136));
            #pragma unroll
            for (int nf = 0; nf < 4; nf++) {
                const uint32_t* pb = &bh[nf>>1][(nf&1)*2];
                #pragma unroll
                for (int mf = 0; mf < 2; mf++)
                    mma16816(accT[mf][nf], ah[mf], pb);
            }
        }
        #pragma unroll
        for (int mf = 0; mf < 2; mf++) {
            int d1 = d1t + wm*32 + mf*16 + gr;
            #pragma unroll
            for (int nf = 0; nf < 4; nf++) {
                int d2 = d2t + wn*32 + nf*8 + tg*2;
                __half2 p0 = __floats2half2_rn(accT[mf][nf][0], accT[mf][nf][1]);
                __half2 p1 = __floats2half2_rn(accT[mf][nf][2], accT[mf][nf][3]);
                *(uint32_t*)&g_Th[((size_t)blk*DIM + d1)*DIM + d2]     = *(uint32_t*)&p0;
                *(uint32_t*)&g_Th[((size_t)blk*DIM + d1 + 8)*DIM + d2] = *(uint32_t*)&p1;
            }
        }
    }
}

// ---------------- K6: in-place prefix of T (fp16, half2-vectorized) -------
__global__ void k_tpref() {   // grid 512, 256 threads; 2 elements per thread
    int idx = blockIdx.x*256 + threadIdx.x;
    int b   = idx >> 15;
    int off = (idx & 32767)*2;
    float2 v[NCH];
    #pragma unroll
    for (int c = 0; c < NCH; c++) {
        uint32_t w = *(const uint32_t*)&g_Th[(((size_t)(b*NCH + c)) << 16) + off];
        v[c] = __half22float2(*(__half2*)&w);
    }
    float gC = __expf(128.f*logf(GAMMA));
    float t0 = 0.f, t1 = 0.f;
    #pragma unroll
    for (int c = 0; c < NCH; c++) {
        __half2 p = __floats2half2_rn(t0, t1);
        *(uint32_t*)&g_Th[(((size_t)(b*NCH + c)) << 16) + off] = *(uint32_t*)&p;
        t0 = t0*gC + v[c].x;
        t1 = t1*gC + v[c].y;
    }
}

// ---------------- K7b: out = S@V + (g^{i+1} Q)@T ---------------------------
#define B1_S(s) ((s)*27136)             // SH +0 (10240), VH +10240 (16896)
#define B2_Q(p) ((p)*20480)             // QH +0, QL +10240
#define B2_T(s) (40960 + (s)*16896)     // TH only
#define SM_KB 91648
__global__ void __launch_bounds__(512,1) k_B(float* __restrict__ out) {
    extern __shared__ char sm[];
    __shared__ float rowGn[CHK];
    int tid = threadIdx.x, lane = tid & 31, warp = tid >> 5;
    int gr = lane >> 2, tg = lane & 3;
    int wm = warp & 3, wn = warp >> 2;   // 4x4 warps, 32(m) x 64(n)
    int blk = blockIdx.x, b = blk >> 5, c = blk & 31, c0 = c*CHK;
    uint32_t smb = smem_u32(sm);

    const __half *Sh = g_Sh + (size_t)blk*CHK*CHK;
    const __half *Vh = g_Vh + (size_t)(b*SEQ + c0)*DIM;
    const __half *Qh = g_Qh + (size_t)(b*SEQ + c0)*DIM;
    const __half *Ql = g_Ql + (size_t)(b*SEQ + c0)*DIM;
    const __half *Th = g_Th + (size_t)blk*65536;

    if (tid < CHK) rowGn[tid] = __expf((float)(tid+1) * logf(GAMMA));

    #pragma unroll
    for (int s = 0; s < 2; s++) {
        uint32_t bb = smb + B1_S(s);
        {
            int row = tid >> 2, c8 = (tid & 3)*8;
            cpa(bb + (uint32_t)(row*PAD + c8)*2, Sh + (size_t)row*CHK + s*32 + c8);
        }
        #pragma unroll
        for (int l = 0; l < 2; l++) {
            int u = tid + l*512;
            int row = u >> 5, c8 = (u & 31)*8;
            cpa(bb + 10240 + (uint32_t)(row*264 + c8)*2, Vh + (size_t)(s*32+row)*DIM + c8);
        }
        CPA_COMMIT;
    }
    __syncthreads();

    float acc[2][8][4] = {};

    // ---- B1: S(hi) @ V, 4 stages, 3-ring, single pass ----
    for (int st = 0; st < 4; st++) {
        if (st < 3) CPA_WAIT(1); else CPA_WAIT(0);
        __syncthreads();
        if (st + 2 < 4) {
            int kn = (st+2)*32;
            uint32_t bb = smb + B1_S((st+2)%3);
            {
                int row = tid >> 2, c8 = (tid & 3)*8;
                cpa(bb + (uint32_t)(row*PAD + c8)*2, Sh + (size_t)row*CHK + kn + c8);
            }
            #pragma unroll
            for (int l = 0; l < 2; l++) {
                int u = tid + l*512;
                int row = u >> 5, c8 = (u & 31)*8;
                cpa(bb + 10240 + (uint32_t)(row*264 + c8)*2, Vh + (size_t)(kn+row)*DIM + c8);
            }
            CPA_COMMIT;
        }
        uint32_t cb = smb + B1_S(st % 3);
        #pragma unroll
        for (int ks = 0; ks < 32; ks += 16) {
            uint32_t ah[2][4];
            #pragma unroll
            for (int mf = 0; mf < 2; mf++)
                ldsm4(ah[mf], addr_am(cb, lane, wm*32 + mf*16, ks, PAD));
            #pragma unroll
            for (int nfp = 0; nfp < 4; nfp++) {
                uint32_t bh[4];
                ldsm4t(bh, baddr(cb + 10240, lane, ks, wn*64 + nfp*16, 264));
                #pragma unroll
                for (int mf = 0; mf < 2; mf++) {
                    mma16816(acc[mf][2*nfp],   ah[mf], bh);
                    mma16816(acc[mf][2*nfp+1], ah[mf], bh+2);
                }
            }
        }
    }
    __syncthreads();   // B1 reads done before B2 overwrites buffers

    // ---- B2: (g^{i+1} Q) @ T_prefix, 8 stages, 3-ring T + 2-buf STS Q ----
    uint4 qhr, qlr;
    {
        int row = tid >> 2, c8 = (tid & 3)*8;
        qhr = *(const uint4*)(Qh + (size_t)row*DIM + c8);
        qlr = *(const uint4*)(Ql + (size_t)row*DIM + c8);
    }
    #pragma unroll
    for (int s = 0; s < 2; s++) {
        uint32_t bb = smb + B2_T(s);
        #pragma unroll
        for (int l = 0; l < 2; l++) {
            int u = tid + l*512;
            int row = u >> 5, c8 = (u & 31)*8;
            cpa(bb + (uint32_t)(row*264 + c8)*2, Th + (size_t)(s*32+row)*DIM + c8);
        }
        CPA_COMMIT;
    }

    for (int st = 0; st < 8; st++) {
        if (st < 7) CPA_WAIT(1); else CPA_WAIT(0);
        char* qb = sm + B2_Q(st & 1);
        {
            int row = tid >> 2, c8 = (tid & 3)*8;
            float f[8]; load8r(f, qhr, qlr);
            float rG = rowGn[row];
            uint32_t hw[4], lw[4];
            #pragma unroll
            for (int i2 = 0; i2 < 4; i2++) hw[i2] = pack2(f[2*i2]*rG, f[2*i2+1]*rG, lw[i2]);
            *(uint4*)(qb + (row*PAD + c8)*2)         = *(uint4*)hw;
            *(uint4*)(qb + 10240 + (row*PAD + c8)*2) = *(uint4*)lw;
        }
        if (st < 7) {
            int en = (st+1)*32;
            int row = tid >> 2, c8 = (tid & 3)*8;
            qhr = *(const uint4*)(Qh + (size_t)row*DIM + en + c8);
            qlr = *(const uint4*)(Ql + (size_t)row*DIM + en + c8);
        }
        __syncthreads();
        if (st + 2 < 8) {
            int en = (st+2)*32;
            uint32_t bb = smb + B2_T((st+2)%3);
            #pragma unroll
            for (int l = 0; l < 2; l++) {
                int u = tid + l*512;
                int row = u >> 5, c8 = (u & 31)*8;
                cpa(bb + (uint32_t)(row*264 + c8)*2, Th + (size_t)(en+row)*DIM + c8);
            }
            CPA_COMMIT;
        }
        uint32_t ab = smb + B2_Q(st & 1);
        uint32_t bb = smb + B2_T(st % 3);
        #pragma unroll
        for (int ks = 0; ks < 32; ks += 16) {
            uint32_t ah[2][4], al[2][4];
            #pragma unroll
            for (int mf = 0; mf < 2; mf++) {
                ldsm4(ah[mf], addr_am(ab, lane, wm*32 + mf*16, ks, PAD));
                ldsm4(al[mf], addr_am(ab + 10240, lane, wm*32 + mf*16, ks, PAD));
            }
            #pragma unroll
            for (int nfp = 0; nfp < 4; nfp++) {
                uint32_t bh[4];
                ldsm4t(bh, baddr(bb, lane, ks, wn*64 + nfp*16, 264));
                #pragma unroll
                for (int mf = 0; mf < 2; mf++) {
                    mma16816(acc[mf][2*nfp],   ah[mf], bh);
                    mma16816(acc[mf][2*nfp+1], ah[mf], bh+2);
                    mma16816(acc[mf][2*nfp],   al[mf], bh);
                    mma16816(acc[mf][2*nfp+1], al[mf], bh+2);
                }
            }
        }
    }

    #pragma unroll
    for (int mf = 0; mf < 2; mf++) {
        int i1 = wm*32 + mf*16 + gr;
        #pragma unroll
        for (int nf = 0; nf < 8; nf++) {
            int n = wn*64 + nf*8 + tg*2;
            *(float2*)&out[(size_t)(b*SEQ + c0 + i1)*DIM + n]     = make_float2(acc[mf][nf][0], acc[mf][nf][1]);
            *(float2*)&out[(size_t)(b*SEQ + c0 + i1 + 8)*DIM + n] = make_float2(acc[mf][nf][2], acc[mf][nf][3]);
        }
    }
}

// -------------------------------------------------------------------------
extern "C" void kernel_launch(void* const* d_in, const int* in_sizes, int n_in,
                              void* d_out, int out_size) {
    const float* xq = (const float*)d_in[0];
    const float* xk = (const float*)d_in[1];
    const float* xv = (const float*)d_in[2];
    const float* Wq = (const float*)d_in[3];
    const float* bq = (const float*)d_in[4];
    const float* Wk = (const float*)d_in[5];
    const float* bk = (const float*)d_in[6];
    const float* Wv = (const float*)d_in[7];
    const float* bv = (const float*)d_in[8];
    float* out = (float*)d_out;

    static int once = 0;
    if (!once) {
        cudaFuncSetAttribute(k_proj_mma, cudaFuncAttributeMaxDynamicSharedMemorySize, SM_PROJ);
        cudaFuncSetAttribute(k_mid,      cudaFuncAttributeMaxDynamicSharedMemorySize, SM_KS);
        cudaFuncSetAttribute(k_B,        cudaFuncAttributeMaxDynamicSharedMemorySize, SM_KB);
        once = 1;
    }

    k_prep  <<<dim3(DIM, 3), 256>>>(Wq, Wk, Wv);
    k_proj_mma<<<dim3(ROWS_TOT/128, DIM/128, 3), 256, SM_PROJ>>>(xq, xk, xv, bq, bk, bv);
    k_mid   <<<BB*NCH, 512, SM_KS>>>();
    k_tpref <<<512, 256>>>();
    k_B     <<<BB*NCH, 512, SM_KB>>>(out);
}